// round 1
// baseline (speedup 1.0000x reference)
#include <cuda_runtime.h>
#include <cuda_bf16.h>
#include <math.h>

#define S_LEN   512
#define NBATCH  128
#define IN_DIM  512
#define HID     1024
#define GDIM    4096   // 4*HID, interleaved as (unit, gate): col g -> gate g&3, unit g>>2
#define NOUT    4

#define BM 64
#define BN 64
#define BKK 32
#define KPAD 40        // smem row stride in bf16 elems (80B): rows shift 16B mod 128B -> ldmatrix conflict-free
#define NTHREADS 256

// ---------------- scratch (static device allocations are allowed) ----------------
__device__ float g_xp[(size_t)S_LEN * NBATCH * GDIM];   // 1 GiB precomputed input projections (+bias)
__device__ float g_hbuf[2][NBATCH * HID];               // double-buffered hidden state
__device__ float g_cbuf[NBATCH * HID];                  // cell state (owner-exclusive per CTA)

struct SmemTiles {
    __nv_bfloat16 a_hi[BM * KPAD];
    __nv_bfloat16 a_lo[BM * KPAD];
    __nv_bfloat16 b_hi[BN * KPAD];
    __nv_bfloat16 b_lo[BN * KPAD];
};
union __align__(16) SmemU {
    SmemTiles t;
    float gates[BM * BN];
};

__device__ __forceinline__ unsigned su32(const void* p){
    return (unsigned)__cvta_generic_to_shared(p);
}
__device__ __forceinline__ void ldmx4(unsigned* r, unsigned addr){
    asm volatile("ldmatrix.sync.aligned.m8n8.x4.shared.b16 {%0,%1,%2,%3}, [%4];"
        : "=r"(r[0]), "=r"(r[1]), "=r"(r[2]), "=r"(r[3]) : "r"(addr));
}
__device__ __forceinline__ void mma_bf16(float* d, const unsigned* a, const unsigned* b){
    asm volatile("mma.sync.aligned.m16n8k16.row.col.f32.bf16.bf16.f32 "
        "{%0,%1,%2,%3},{%4,%5,%6,%7},{%8,%9},{%0,%1,%2,%3};"
        : "+f"(d[0]), "+f"(d[1]), "+f"(d[2]), "+f"(d[3])
        : "r"(a[0]), "r"(a[1]), "r"(a[2]), "r"(a[3]), "r"(b[0]), "r"(b[1]));
}
// split fp32 -> hi bf16 (rn) + lo bf16 of remainder; stores 2 elems packed as bf16x2
__device__ __forceinline__ void split_pair(float x, float y, __nv_bfloat16* hi, __nv_bfloat16* lo){
    __nv_bfloat16 hx = __float2bfloat16(x);
    __nv_bfloat16 hy = __float2bfloat16(y);
    float lx = x - __bfloat162float(hx);
    float ly = y - __bfloat162float(hy);
    *reinterpret_cast<__nv_bfloat162*>(hi) = __halves2bfloat162(hx, hy);
    *reinterpret_cast<__nv_bfloat162*>(lo) = __halves2bfloat162(__float2bfloat16(lx), __float2bfloat16(ly));
}
__device__ __forceinline__ float sigmoidf_(float x){ return 1.0f / (1.0f + expf(-x)); }

// ---------------- fused GEMM kernel ----------------
// MODE 0: x_proj = inputs @ W_ih^T (+ b_ih + b_hh), written interleaved into g_xp
// MODE 1: gates  = h @ W_hh^T + x_proj[s]; fused LSTM elementwise; writes h_next, c
// Both compute C[M,N] = A[M,K] * Wrows(gather)[N,K]^T in split-bf16 (3 MMA passes).
template<int KDIM, int MODE>
__global__ __launch_bounds__(NTHREADS)
void lstm_gemm(const float* __restrict__ Ain, const float* __restrict__ Wg,
               const float* __restrict__ bias_ih, const float* __restrict__ bias_hh,
               int s)
{
    __shared__ SmemU sm;
    const int tid   = threadIdx.x;
    const int lane  = tid & 31;
    const int wid   = tid >> 5;
    const int warp_m = wid >> 2;   // 0..1 (32 rows each)
    const int warp_n = wid & 3;    // 0..3 (16 cols each)
    const int m0 = blockIdx.y * BM;
    const int n0 = blockIdx.x * BN;

    const float* A = (MODE == 0) ? Ain : g_hbuf[s & 1];

    float acc[2][2][4];
    #pragma unroll
    for (int i = 0; i < 2; i++)
        #pragma unroll
        for (int j = 0; j < 2; j++)
            #pragma unroll
            for (int k = 0; k < 4; k++) acc[i][j][k] = 0.0f;

    const int KITERS = KDIM / BKK;

    // per-thread load coords: 2 float4 loads per tile (64 rows x 8 float4-cols)
    int lr[2], lc[2];
    size_t arowoff[2], browoff[2];
    #pragma unroll
    for (int i = 0; i < 2; i++){
        int idx = tid + i * NTHREADS;
        lr[i] = idx >> 3;
        lc[i] = (idx & 7) << 2;
        arowoff[i] = (size_t)(m0 + lr[i]) * KDIM;
        int g = n0 + lr[i];                               // interleaved gate column
        browoff[i] = (size_t)((g & 3) * HID + (g >> 2)) * KDIM;  // gather W row
    }

    float4 pa[2], pb[2];
    #pragma unroll
    for (int i = 0; i < 2; i++){
        pa[i] = *reinterpret_cast<const float4*>(A  + arowoff[i] + lc[i]);
        pb[i] = *reinterpret_cast<const float4*>(Wg + browoff[i] + lc[i]);
    }

    for (int kt = 0; kt < KITERS; kt++){
        // store prefetched tile (fp32 -> hi/lo bf16)
        #pragma unroll
        for (int i = 0; i < 2; i++){
            int base = lr[i] * KPAD + lc[i];
            split_pair(pa[i].x, pa[i].y, &sm.t.a_hi[base],     &sm.t.a_lo[base]);
            split_pair(pa[i].z, pa[i].w, &sm.t.a_hi[base + 2], &sm.t.a_lo[base + 2]);
            split_pair(pb[i].x, pb[i].y, &sm.t.b_hi[base],     &sm.t.b_lo[base]);
            split_pair(pb[i].z, pb[i].w, &sm.t.b_hi[base + 2], &sm.t.b_lo[base + 2]);
        }
        __syncthreads();

        // prefetch next K-tile into registers (latency hidden behind MMAs)
        if (kt + 1 < KITERS){
            int k0 = (kt + 1) * BKK;
            #pragma unroll
            for (int i = 0; i < 2; i++){
                pa[i] = *reinterpret_cast<const float4*>(A  + arowoff[i] + k0 + lc[i]);
                pb[i] = *reinterpret_cast<const float4*>(Wg + browoff[i] + k0 + lc[i]);
            }
        }

        // compute: 2 x k16 per K-tile, 3 split passes each
        #pragma unroll
        for (int kk = 0; kk < 2; kk++){
            const int lrow = lane & 15;
            const int lcol = kk * 16 + ((lane >> 4) << 3);
            unsigned ah[2][4], al[2][4];
            #pragma unroll
            for (int mt = 0; mt < 2; mt++){
                int r = warp_m * 32 + mt * 16 + lrow;
                ldmx4(ah[mt], su32(&sm.t.a_hi[r * KPAD + lcol]));
                ldmx4(al[mt], su32(&sm.t.a_lo[r * KPAD + lcol]));
            }
            unsigned bh[2][2], bl[2][2];
            {
                int r = warp_n * 16 + lrow;
                unsigned t4[4];
                ldmx4(t4, su32(&sm.t.b_hi[r * KPAD + lcol]));
                bh[0][0] = t4[0]; bh[1][0] = t4[1]; bh[0][1] = t4[2]; bh[1][1] = t4[3];
                ldmx4(t4, su32(&sm.t.b_lo[r * KPAD + lcol]));
                bl[0][0] = t4[0]; bl[1][0] = t4[1]; bl[0][1] = t4[2]; bl[1][1] = t4[3];
            }
            #pragma unroll
            for (int mt = 0; mt < 2; mt++)
                #pragma unroll
                for (int nt = 0; nt < 2; nt++){
                    mma_bf16(acc[mt][nt], ah[mt], bh[nt]);   // hi*hi
                    mma_bf16(acc[mt][nt], al[mt], bh[nt]);   // lo*hi
                    mma_bf16(acc[mt][nt], ah[mt], bl[nt]);   // hi*lo
                }
        }
        __syncthreads();
    }

    if (MODE == 0){
        // epilogue: add combined bias, write x_proj (interleaved columns)
        #pragma unroll
        for (int mt = 0; mt < 2; mt++)
            #pragma unroll
            for (int nt = 0; nt < 2; nt++)
                #pragma unroll
                for (int pp = 0; pp < 2; pp++){
                    int row = m0 + warp_m * 32 + mt * 16 + (lane >> 2) + 8 * pp;
                    int col = n0 + warp_n * 16 + nt * 8 + 2 * (lane & 3);
                    int r0 = (col & 3) * HID + (col >> 2);
                    int r1 = ((col + 1) & 3) * HID + ((col + 1) >> 2);
                    float* dst = &g_xp[(size_t)row * GDIM + col];
                    dst[0] = acc[mt][nt][2 * pp]     + bias_ih[r0] + bias_hh[r0];
                    dst[1] = acc[mt][nt][2 * pp + 1] + bias_ih[r1] + bias_hh[r1];
                }
    } else {
        // stage gates in smem (union over the mma tiles), then fused elementwise
        #pragma unroll
        for (int mt = 0; mt < 2; mt++)
            #pragma unroll
            for (int nt = 0; nt < 2; nt++)
                #pragma unroll
                for (int pp = 0; pp < 2; pp++){
                    int row = warp_m * 32 + mt * 16 + (lane >> 2) + 8 * pp;
                    int col = warp_n * 16 + nt * 8 + 2 * (lane & 3);
                    sm.gates[row * BN + col]     = acc[mt][nt][2 * pp];
                    sm.gates[row * BN + col + 1] = acc[mt][nt][2 * pp + 1];
                }
        __syncthreads();
        float* Hnext = g_hbuf[(s + 1) & 1];
        const float* xpbase = &g_xp[(size_t)(s * NBATCH + m0) * GDIM + n0];
        for (int i = tid; i < BM * (BN / 4); i += NTHREADS){
            int m = i >> 4, u = i & 15;   // 16 units per CTA
            float4 gv = *reinterpret_cast<float4*>(&sm.gates[m * BN + u * 4]);
            float4 xv = *reinterpret_cast<const float4*>(xpbase + (size_t)m * GDIM + u * 4);
            float ig = sigmoidf_(gv.x + xv.x);
            float fg = sigmoidf_(gv.y + xv.y);
            float gg = tanhf(gv.z + xv.z);
            float og = sigmoidf_(gv.w + xv.w);
            int hidx = (m0 + m) * HID + (n0 >> 2) + u;
            float cn = fg * g_cbuf[hidx] + ig * gg;
            g_cbuf[hidx] = cn;
            Hnext[hidx] = og * tanhf(cn);
        }
    }
}

// ---------------- small kernels ----------------
__global__ void init_state(const float* __restrict__ h0, const float* __restrict__ c0){
    int i = blockIdx.x * blockDim.x + threadIdx.x;
    if (i < NBATCH * HID){
        g_hbuf[0][i] = h0[i];
        g_cbuf[i]    = c0[i];
    }
}

__global__ void lstm_decode(const float* __restrict__ W_dec, const float* __restrict__ b_dec,
                            float* __restrict__ out){
    __shared__ float wsh[NOUT * HID];
    __shared__ float lsh[NOUT * NBATCH];
    __shared__ float red[2 * NOUT];
    for (int i = threadIdx.x; i < NOUT * HID; i += blockDim.x) wsh[i] = W_dec[i];
    __syncthreads();
    int b = threadIdx.x;   // 128 threads, one per batch row
    float a0 = b_dec[0], a1 = b_dec[1], a2 = b_dec[2], a3 = b_dec[3];
    const float* hrow = &g_hbuf[0][b * HID];   // after 512 steps, h lives in buffer 0
    for (int h = 0; h < HID; h++){
        float hv = hrow[h];
        a0 += hv * wsh[h];
        a1 += hv * wsh[HID + h];
        a2 += hv * wsh[2 * HID + h];
        a3 += hv * wsh[3 * HID + h];
    }
    lsh[0 * NBATCH + b] = a0; lsh[1 * NBATCH + b] = a1;
    lsh[2 * NBATCH + b] = a2; lsh[3 * NBATCH + b] = a3;
    __syncthreads();
    if (threadIdx.x < NOUT){
        int o = threadIdx.x;
        float m = -1e30f;
        for (int j = 0; j < NBATCH; j++) m = fmaxf(m, lsh[o * NBATCH + j]);
        float sum = 0.0f;
        for (int j = 0; j < NBATCH; j++) sum += expf(lsh[o * NBATCH + j] - m);
        red[o] = m; red[NOUT + o] = sum;
    }
    __syncthreads();
    #pragma unroll
    for (int o = 0; o < NOUT; o++)
        out[b * NOUT + o] = expf(lsh[o * NBATCH + b] - red[o]) / red[NOUT + o];
}

// ---------------- launch ----------------
extern "C" void kernel_launch(void* const* d_in, const int* in_sizes, int n_in,
                              void* d_out, int out_size)
{
    const float* inputs = (const float*)d_in[0];
    const float* h0     = (const float*)d_in[1];
    const float* c0     = (const float*)d_in[2];
    const float* W_ih   = (const float*)d_in[3];
    const float* W_hh   = (const float*)d_in[4];
    const float* b_ih   = (const float*)d_in[5];
    const float* b_hh   = (const float*)d_in[6];
    const float* W_dec  = (const float*)d_in[7];
    const float* b_dec  = (const float*)d_in[8];
    float* out = (float*)d_out;

    init_state<<<(NBATCH * HID + 255) / 256, 256>>>(h0, c0);

    // Phase 1: x_proj for all timesteps (M=65536, N=4096, K=512)
    dim3 g1(GDIM / BN, (S_LEN * NBATCH) / BM);
    lstm_gemm<IN_DIM, 0><<<g1, NTHREADS>>>(inputs, W_ih, b_ih, b_hh, 0);

    // Recurrence: 512 dependent step kernels (graph edges serialize them)
    dim3 gs(GDIM / BN, NBATCH / BM);
    for (int s = 0; s < S_LEN; s++){
        lstm_gemm<HID, 1><<<gs, NTHREADS>>>(nullptr, W_hh, nullptr, nullptr, s);
    }

    lstm_decode<<<1, 128>>>(W_dec, b_dec, out);
}

// round 2
// speedup vs baseline: 1.0082x; 1.0082x over previous
#include <cuda_runtime.h>
#include <cuda_bf16.h>
#include <math.h>

#define S_LEN   512
#define NBATCH  128
#define IN_DIM  512
#define HID     1024
#define GDIM    4096   // 4*HID, interleaved: col g -> gate g&3, unit g>>2
#define NOUT    4

// ---------------- phase-1 GEMM tiling (unchanged from R1) ----------------
#define BM 64
#define BN 64
#define BKK 32
#define KPAD 40
#define NTHREADS 256

// ---------------- persistent recurrence tiling ----------------
#define PBN 32                  // gate-cols per CTA
#define PGRID (GDIM / PBN)      // 128 CTAs (all resident)
#define PBK 64                  // K chunk
#define WPAD (HID + 8)          // 1032 (row stride shifts 16B mod 128B)
#define APAD (PBK + 8)          // 72
#define PKITERS (HID / PBK)     // 16
#define PTHREADS 256

// smem byte offsets (persistent kernel, dynamic smem)
#define WSLICE_B  (PBN * WPAD * 2)        // 66048
#define OFF_WHI   0
#define OFF_WLO   (OFF_WHI + WSLICE_B)
#define ABUF_B    (NBATCH * APAD * 2)     // 18432
#define OFF_AHI   (OFF_WLO + WSLICE_B)    // 132096
#define OFF_ALO   (OFF_AHI + 2 * ABUF_B)  // 168960
#define PSMEM_TOTAL (OFF_ALO + 2 * ABUF_B) // 205824
#define OFF_GATES OFF_AHI                 // reuse A region for gate staging

// ---------------- device globals ----------------
__device__ float g_xp[(size_t)S_LEN * NBATCH * GDIM];    // precomputed x_proj (+biases)
__device__ __nv_bfloat16 g_hhi[2][NBATCH * HID];         // hidden, hi part, double-buffered
__device__ __nv_bfloat16 g_hlo[2][NBATCH * HID];         // hidden, lo part
__device__ float g_cbuf[NBATCH * HID];                   // cell (CTA-exclusive slices)
__device__ int g_bar_count;
__device__ volatile int g_bar_phase;

// ---------------- helpers ----------------
__device__ __forceinline__ unsigned su32(const void* p){
    return (unsigned)__cvta_generic_to_shared(p);
}
__device__ __forceinline__ void ldmx4(unsigned* r, unsigned addr){
    asm volatile("ldmatrix.sync.aligned.m8n8.x4.shared.b16 {%0,%1,%2,%3}, [%4];"
        : "=r"(r[0]), "=r"(r[1]), "=r"(r[2]), "=r"(r[3]) : "r"(addr));
}
__device__ __forceinline__ void mma_bf16(float* d, const unsigned* a, const unsigned* b){
    asm volatile("mma.sync.aligned.m16n8k16.row.col.f32.bf16.bf16.f32 "
        "{%0,%1,%2,%3},{%4,%5,%6,%7},{%8,%9},{%0,%1,%2,%3};"
        : "+f"(d[0]), "+f"(d[1]), "+f"(d[2]), "+f"(d[3])
        : "r"(a[0]), "r"(a[1]), "r"(a[2]), "r"(a[3]), "r"(b[0]), "r"(b[1]));
}
__device__ __forceinline__ void split_pair(float x, float y, __nv_bfloat16* hi, __nv_bfloat16* lo){
    __nv_bfloat16 hx = __float2bfloat16(x);
    __nv_bfloat16 hy = __float2bfloat16(y);
    float lx = x - __bfloat162float(hx);
    float ly = y - __bfloat162float(hy);
    *reinterpret_cast<__nv_bfloat162*>(hi) = __halves2bfloat162(hx, hy);
    *reinterpret_cast<__nv_bfloat162*>(lo) = __halves2bfloat162(__float2bfloat16(lx), __float2bfloat16(ly));
}
__device__ __forceinline__ float sigmoidf_(float x){ return 1.0f / (1.0f + expf(-x)); }

__device__ __forceinline__ void cpasync16(unsigned saddr, const void* g){
    asm volatile("cp.async.cg.shared.global [%0], [%1], 16;" :: "r"(saddr), "l"(g));
}
#define CP_COMMIT() asm volatile("cp.async.commit_group;")
#define CP_WAIT1()  asm volatile("cp.async.wait_group 1;")
#define CP_WAIT0()  asm volatile("cp.async.wait_group 0;")

// sense-reversing grid barrier (all PGRID CTAs resident by construction)
__device__ __forceinline__ void grid_barrier(int* sense){
    __threadfence();
    __syncthreads();
    if (threadIdx.x == 0){
        int target = *sense ^ 1;
        if (atomicAdd(&g_bar_count, 1) == PGRID - 1){
            atomicExch(&g_bar_count, 0);
            __threadfence();
            g_bar_phase = target;
        } else {
            while (g_bar_phase != target) __nanosleep(40);
        }
        *sense = target;
    }
    __syncthreads();
    __threadfence();
}

// ---------------- phase 1: x_proj = inputs @ W_ih^T + b_ih + b_hh ----------------
struct SmemTiles {
    __nv_bfloat16 a_hi[BM * KPAD];
    __nv_bfloat16 a_lo[BM * KPAD];
    __nv_bfloat16 b_hi[BN * KPAD];
    __nv_bfloat16 b_lo[BN * KPAD];
};

__global__ __launch_bounds__(NTHREADS)
void xproj_gemm(const float* __restrict__ Ain, const float* __restrict__ Wg,
                const float* __restrict__ bias_ih, const float* __restrict__ bias_hh)
{
    __shared__ SmemTiles sm;
    const int tid   = threadIdx.x;
    const int lane  = tid & 31;
    const int wid   = tid >> 5;
    const int warp_m = wid >> 2;
    const int warp_n = wid & 3;
    const int m0 = blockIdx.y * BM;
    const int n0 = blockIdx.x * BN;
    const int KDIM = IN_DIM;

    float acc[2][2][4];
    #pragma unroll
    for (int i = 0; i < 2; i++)
        #pragma unroll
        for (int j = 0; j < 2; j++)
            #pragma unroll
            for (int k = 0; k < 4; k++) acc[i][j][k] = 0.0f;

    const int KITERS = KDIM / BKK;
    int lr[2], lc[2];
    size_t arowoff[2], browoff[2];
    #pragma unroll
    for (int i = 0; i < 2; i++){
        int idx = tid + i * NTHREADS;
        lr[i] = idx >> 3;
        lc[i] = (idx & 7) << 2;
        arowoff[i] = (size_t)(m0 + lr[i]) * KDIM;
        int g = n0 + lr[i];
        browoff[i] = (size_t)((g & 3) * HID + (g >> 2)) * KDIM;
    }

    float4 pa[2], pb[2];
    #pragma unroll
    for (int i = 0; i < 2; i++){
        pa[i] = *reinterpret_cast<const float4*>(Ain + arowoff[i] + lc[i]);
        pb[i] = *reinterpret_cast<const float4*>(Wg  + browoff[i] + lc[i]);
    }

    for (int kt = 0; kt < KITERS; kt++){
        #pragma unroll
        for (int i = 0; i < 2; i++){
            int base = lr[i] * KPAD + lc[i];
            split_pair(pa[i].x, pa[i].y, &sm.a_hi[base],     &sm.a_lo[base]);
            split_pair(pa[i].z, pa[i].w, &sm.a_hi[base + 2], &sm.a_lo[base + 2]);
            split_pair(pb[i].x, pb[i].y, &sm.b_hi[base],     &sm.b_lo[base]);
            split_pair(pb[i].z, pb[i].w, &sm.b_hi[base + 2], &sm.b_lo[base + 2]);
        }
        __syncthreads();

        if (kt + 1 < KITERS){
            int k0 = (kt + 1) * BKK;
            #pragma unroll
            for (int i = 0; i < 2; i++){
                pa[i] = *reinterpret_cast<const float4*>(Ain + arowoff[i] + k0 + lc[i]);
                pb[i] = *reinterpret_cast<const float4*>(Wg  + browoff[i] + k0 + lc[i]);
            }
        }

        #pragma unroll
        for (int kk = 0; kk < 2; kk++){
            const int lrow = lane & 15;
            const int lcol = kk * 16 + ((lane >> 4) << 3);
            unsigned ah[2][4], al[2][4];
            #pragma unroll
            for (int mt = 0; mt < 2; mt++){
                int r = warp_m * 32 + mt * 16 + lrow;
                ldmx4(ah[mt], su32(&sm.a_hi[r * KPAD + lcol]));
                ldmx4(al[mt], su32(&sm.a_lo[r * KPAD + lcol]));
            }
            unsigned bh[2][2], bl[2][2];
            {
                int r = warp_n * 16 + lrow;
                unsigned t4[4];
                ldmx4(t4, su32(&sm.b_hi[r * KPAD + lcol]));
                bh[0][0] = t4[0]; bh[1][0] = t4[1]; bh[0][1] = t4[2]; bh[1][1] = t4[3];
                ldmx4(t4, su32(&sm.b_lo[r * KPAD + lcol]));
                bl[0][0] = t4[0]; bl[1][0] = t4[1]; bl[0][1] = t4[2]; bl[1][1] = t4[3];
            }
            #pragma unroll
            for (int mt = 0; mt < 2; mt++)
                #pragma unroll
                for (int nt = 0; nt < 2; nt++){
                    mma_bf16(acc[mt][nt], ah[mt], bh[nt]);
                    mma_bf16(acc[mt][nt], al[mt], bh[nt]);
                    mma_bf16(acc[mt][nt], ah[mt], bl[nt]);
                }
        }
        __syncthreads();
    }

    #pragma unroll
    for (int mt = 0; mt < 2; mt++)
        #pragma unroll
        for (int nt = 0; nt < 2; nt++)
            #pragma unroll
            for (int pp = 0; pp < 2; pp++){
                int row = m0 + warp_m * 32 + mt * 16 + (lane >> 2) + 8 * pp;
                int col = n0 + warp_n * 16 + nt * 8 + 2 * (lane & 3);
                int r0 = (col & 3) * HID + (col >> 2);
                int r1 = ((col + 1) & 3) * HID + ((col + 1) >> 2);
                float* dst = &g_xp[(size_t)row * GDIM + col];
                dst[0] = acc[mt][nt][2 * pp]     + bias_ih[r0] + bias_hh[r0];
                dst[1] = acc[mt][nt][2 * pp + 1] + bias_ih[r1] + bias_hh[r1];
            }
}

// ---------------- persistent recurrence kernel ----------------
__device__ __forceinline__ void load_chunk(char* smbase, int b, int kt, int s, int tid){
    const __nv_bfloat16* hh = g_hhi[s & 1];
    const __nv_bfloat16* hl = g_hlo[s & 1];
    char* ahi = smbase + OFF_AHI + b * ABUF_B;
    char* alo = smbase + OFF_ALO + b * ABUF_B;
    #pragma unroll
    for (int j = 0; j < 4; j++){
        int c   = tid + j * PTHREADS;   // 0..1023 : 16B chunk id
        int row = c >> 3;
        int cc  = c & 7;
        const __nv_bfloat16* gh = hh + (size_t)row * HID + kt * PBK + cc * 8;
        const __nv_bfloat16* gl = hl + (size_t)row * HID + kt * PBK + cc * 8;
        cpasync16(su32(ahi + row * (APAD * 2) + cc * 16), gh);
        cpasync16(su32(alo + row * (APAD * 2) + cc * 16), gl);
    }
}

__global__ __launch_bounds__(PTHREADS, 1)
void lstm_persistent(const float* __restrict__ W_hh)
{
    extern __shared__ char smbase[];
    const int tid  = threadIdx.x;
    const int lane = tid & 31;
    const int wid  = tid >> 5;
    const int warp_m = wid >> 1;   // 0..3 (32 rows each)
    const int warp_n = wid & 1;    // 0..1 (16 cols each)
    const int n0 = blockIdx.x * PBN;

    __nv_bfloat16* w_hi = (__nv_bfloat16*)(smbase + OFF_WHI);
    __nv_bfloat16* w_lo = (__nv_bfloat16*)(smbase + OFF_WLO);

    // one-time: gather + split this CTA's W_hh slice into SMEM
    for (int idx = tid; idx < PBN * (HID / 4); idx += PTHREADS){
        int j  = idx >> 8;     // 0..31 slice row (interleaved gate col)
        int k4 = idx & 255;
        int g  = n0 + j;
        const float4 v = *reinterpret_cast<const float4*>(
            W_hh + (size_t)((g & 3) * HID + (g >> 2)) * HID + k4 * 4);
        int base = j * WPAD + k4 * 4;
        split_pair(v.x, v.y, &w_hi[base],     &w_lo[base]);
        split_pair(v.z, v.w, &w_hi[base + 2], &w_lo[base + 2]);
    }
    __syncthreads();

    int sense = 0;
    for (int s = 0; s < S_LEN; s++){
        float acc[2][2][4];
        #pragma unroll
        for (int i = 0; i < 2; i++)
            #pragma unroll
            for (int j = 0; j < 2; j++)
                #pragma unroll
                for (int k = 0; k < 4; k++) acc[i][j][k] = 0.0f;

        load_chunk(smbase, 0, 0, s, tid);
        CP_COMMIT();

        for (int kt = 0; kt < PKITERS; kt++){
            if (kt + 1 < PKITERS){
                load_chunk(smbase, (kt + 1) & 1, kt + 1, s, tid);
                CP_COMMIT();
                CP_WAIT1();
            } else {
                CP_WAIT0();
            }
            __syncthreads();

            const __nv_bfloat16* ah_t = (const __nv_bfloat16*)(smbase + OFF_AHI + (kt & 1) * ABUF_B);
            const __nv_bfloat16* al_t = (const __nv_bfloat16*)(smbase + OFF_ALO + (kt & 1) * ABUF_B);

            #pragma unroll
            for (int kk = 0; kk < PBK / 16; kk++){
                const int lrow = lane & 15;
                const int lcol = kk * 16 + ((lane >> 4) << 3);
                unsigned ah[2][4], al[2][4];
                #pragma unroll
                for (int mt = 0; mt < 2; mt++){
                    int r = warp_m * 32 + mt * 16 + lrow;
                    ldmx4(ah[mt], su32(&ah_t[r * APAD + lcol]));
                    ldmx4(al[mt], su32(&al_t[r * APAD + lcol]));
                }
                unsigned bh[2][2], bl[2][2];
                {
                    int r = warp_n * 16 + lrow;
                    unsigned t4[4];
                    ldmx4(t4, su32(&w_hi[r * WPAD + kt * PBK + lcol]));
                    bh[0][0] = t4[0]; bh[1][0] = t4[1]; bh[0][1] = t4[2]; bh[1][1] = t4[3];
                    ldmx4(t4, su32(&w_lo[r * WPAD + kt * PBK + lcol]));
                    bl[0][0] = t4[0]; bl[1][0] = t4[1]; bl[0][1] = t4[2]; bl[1][1] = t4[3];
                }
                #pragma unroll
                for (int mt = 0; mt < 2; mt++)
                    #pragma unroll
                    for (int nt = 0; nt < 2; nt++){
                        mma_bf16(acc[mt][nt], ah[mt], bh[nt]);
                        mma_bf16(acc[mt][nt], al[mt], bh[nt]);
                        mma_bf16(acc[mt][nt], ah[mt], bl[nt]);
                    }
            }
            __syncthreads();   // compute done before next chunk overwrites buffer
        }

        // ---- epilogue: stage gates, fused LSTM elementwise ----
        float* gates = (float*)(smbase + OFF_GATES);
        #pragma unroll
        for (int mt = 0; mt < 2; mt++)
            #pragma unroll
            for (int nt = 0; nt < 2; nt++)
                #pragma unroll
                for (int pp = 0; pp < 2; pp++){
                    int row = warp_m * 32 + mt * 16 + (lane >> 2) + 8 * pp;
                    int col = warp_n * 16 + nt * 8 + 2 * (lane & 3);
                    gates[row * PBN + col]     = acc[mt][nt][2 * pp];
                    gates[row * PBN + col + 1] = acc[mt][nt][2 * pp + 1];
                }
        __syncthreads();

        __nv_bfloat16* hh_n = g_hhi[(s + 1) & 1];
        __nv_bfloat16* hl_n = g_hlo[(s + 1) & 1];
        const float* xpbase = &g_xp[(size_t)((size_t)s * NBATCH) * GDIM + n0];
        for (int i = tid; i < NBATCH * (PBN / 4); i += PTHREADS){
            int m = i >> 3;        // batch row
            int u = i & 7;         // unit within CTA slice
            float4 gv = *reinterpret_cast<float4*>(&gates[m * PBN + u * 4]);
            float4 xv = *reinterpret_cast<const float4*>(xpbase + (size_t)m * GDIM + u * 4);
            float ig = sigmoidf_(gv.x + xv.x);
            float fg = sigmoidf_(gv.y + xv.y);
            float gg = tanhf(gv.z + xv.z);
            float og = sigmoidf_(gv.w + xv.w);
            int hidx = m * HID + (n0 >> 2) + u;
            float cn = fg * g_cbuf[hidx] + ig * gg;
            g_cbuf[hidx] = cn;
            float hv = og * tanhf(cn);
            __nv_bfloat16 hb = __float2bfloat16(hv);
            hh_n[hidx] = hb;
            hl_n[hidx] = __float2bfloat16(hv - __bfloat162float(hb));
        }

        grid_barrier(&sense);
    }
}

// ---------------- small kernels ----------------
__global__ void init_state(const float* __restrict__ h0, const float* __restrict__ c0){
    int i = blockIdx.x * blockDim.x + threadIdx.x;
    if (i < NBATCH * HID){
        float hv = h0[i];
        __nv_bfloat16 hb = __float2bfloat16(hv);
        g_hhi[0][i] = hb;
        g_hlo[0][i] = __float2bfloat16(hv - __bfloat162float(hb));
        g_cbuf[i]   = c0[i];
    }
    if (i == 0){ g_bar_count = 0; g_bar_phase = 0; }
}

__global__ void lstm_decode(const float* __restrict__ W_dec, const float* __restrict__ b_dec,
                            float* __restrict__ out){
    __shared__ float wsh[NOUT * HID];
    __shared__ float lsh[NOUT * NBATCH];
    __shared__ float red[2 * NOUT];
    for (int i = threadIdx.x; i < NOUT * HID; i += blockDim.x) wsh[i] = W_dec[i];
    __syncthreads();
    int b = threadIdx.x;   // 128 threads, one per batch row
    float a0 = b_dec[0], a1 = b_dec[1], a2 = b_dec[2], a3 = b_dec[3];
    const __nv_bfloat16* hi = &g_hhi[0][b * HID];   // after 512 steps h is in buffer 0
    const __nv_bfloat16* lo = &g_hlo[0][b * HID];
    for (int h = 0; h < HID; h++){
        float hv = __bfloat162float(hi[h]) + __bfloat162float(lo[h]);
        a0 += hv * wsh[h];
        a1 += hv * wsh[HID + h];
        a2 += hv * wsh[2 * HID + h];
        a3 += hv * wsh[3 * HID + h];
    }
    lsh[0 * NBATCH + b] = a0; lsh[1 * NBATCH + b] = a1;
    lsh[2 * NBATCH + b] = a2; lsh[3 * NBATCH + b] = a3;
    __syncthreads();
    if (threadIdx.x < NOUT){
        int o = threadIdx.x;
        float m = -1e30f;
        for (int j = 0; j < NBATCH; j++) m = fmaxf(m, lsh[o * NBATCH + j]);
        float sum = 0.0f;
        for (int j = 0; j < NBATCH; j++) sum += expf(lsh[o * NBATCH + j] - m);
        red[o] = m; red[NOUT + o] = sum;
    }
    __syncthreads();
    #pragma unroll
    for (int o = 0; o < NOUT; o++)
        out[b * NOUT + o] = expf(lsh[o * NBATCH + b] - red[o]) / red[NOUT + o];
}

// ---------------- launch ----------------
extern "C" void kernel_launch(void* const* d_in, const int* in_sizes, int n_in,
                              void* d_out, int out_size)
{
    const float* inputs = (const float*)d_in[0];
    const float* h0     = (const float*)d_in[1];
    const float* c0     = (const float*)d_in[2];
    const float* W_ih   = (const float*)d_in[3];
    const float* W_hh   = (const float*)d_in[4];
    const float* b_ih   = (const float*)d_in[5];
    const float* b_hh   = (const float*)d_in[6];
    const float* W_dec  = (const float*)d_in[7];
    const float* b_dec  = (const float*)d_in[8];
    float* out = (float*)d_out;

    cudaFuncSetAttribute(lstm_persistent,
                         cudaFuncAttributeMaxDynamicSharedMemorySize, PSMEM_TOTAL);

    init_state<<<(NBATCH * HID + 255) / 256, 256>>>(h0, c0);

    // Phase 1: x_proj for all timesteps (M=65536, N=4096, K=512)
    dim3 g1(GDIM / BN, (S_LEN * NBATCH) / BM);
    xproj_gemm<<<g1, NTHREADS>>>(inputs, W_ih, b_ih, b_hh);

    // Recurrence: one persistent kernel, 512 internally-synchronized steps
    lstm_persistent<<<PGRID, PTHREADS, PSMEM_TOTAL>>>(W_hh);

    lstm_decode<<<1, 128>>>(W_dec, b_dec, out);
}

// round 3
// speedup vs baseline: 1.0124x; 1.0042x over previous
#include <cuda_runtime.h>
#include <cuda_bf16.h>
#include <math.h>

#define S_LEN   512
#define NBATCH  128
#define IN_DIM  512
#define HID     1024
#define GDIM    4096   // 4*HID, interleaved: col g -> gate g&3, unit g>>2
#define NOUT    4

// ---------------- phase-1 GEMM tiling (unchanged from R1) ----------------
#define BM 64
#define BN 64
#define BKK 32
#define KPAD 40
#define NTHREADS 256

// ---------------- persistent recurrence tiling ----------------
#define PBN 32                  // gate-cols per CTA
#define PGRID (GDIM / PBN)      // 128 CTAs (all resident)
#define PBK 64                  // K chunk
#define WPAD (HID + 8)          // 1032 (row stride shifts 16B mod 128B)
#define APAD (PBK + 8)          // 72
#define PKITERS (HID / PBK)     // 16
#define PTHREADS 256

// smem byte offsets (persistent kernel, dynamic smem)
#define WSLICE_B  (PBN * WPAD * 2)        // 66048
#define OFF_WHI   0
#define OFF_WLO   (OFF_WHI + WSLICE_B)
#define ABUF_B    (NBATCH * APAD * 2)     // 18432
#define OFF_AHI   (OFF_WLO + WSLICE_B)    // 132096
#define OFF_ALO   (OFF_AHI + 2 * ABUF_B)  // 168960
#define PSMEM_TOTAL (OFF_ALO + 2 * ABUF_B) // 205824
#define OFF_GATES OFF_AHI                 // reuse A region for gate staging

// ---------------- device globals ----------------
__device__ float g_xp[(size_t)S_LEN * NBATCH * GDIM];    // precomputed x_proj (+biases)
__device__ __nv_bfloat16 g_hhi[2][NBATCH * HID];         // hidden, hi part, double-buffered
__device__ __nv_bfloat16 g_hlo[2][NBATCH * HID];         // hidden, lo part
__device__ float g_cbuf[NBATCH * HID];                   // cell (CTA-exclusive slices)
__device__ int g_bar_count;
__device__ volatile int g_bar_phase;

// ---------------- helpers ----------------
__device__ __forceinline__ unsigned su32(const void* p){
    return (unsigned)__cvta_generic_to_shared(p);
}
__device__ __forceinline__ void ldmx4(unsigned* r, unsigned addr){
    asm volatile("ldmatrix.sync.aligned.m8n8.x4.shared.b16 {%0,%1,%2,%3}, [%4];"
        : "=r"(r[0]), "=r"(r[1]), "=r"(r[2]), "=r"(r[3]) : "r"(addr));
}
__device__ __forceinline__ void mma_bf16(float* d, const unsigned* a, const unsigned* b){
    asm volatile("mma.sync.aligned.m16n8k16.row.col.f32.bf16.bf16.f32 "
        "{%0,%1,%2,%3},{%4,%5,%6,%7},{%8,%9},{%0,%1,%2,%3};"
        : "+f"(d[0]), "+f"(d[1]), "+f"(d[2]), "+f"(d[3])
        : "r"(a[0]), "r"(a[1]), "r"(a[2]), "r"(a[3]), "r"(b[0]), "r"(b[1]));
}
__device__ __forceinline__ void split_pair(float x, float y, __nv_bfloat16* hi, __nv_bfloat16* lo){
    __nv_bfloat16 hx = __float2bfloat16(x);
    __nv_bfloat16 hy = __float2bfloat16(y);
    float lx = x - __bfloat162float(hx);
    float ly = y - __bfloat162float(hy);
    *reinterpret_cast<__nv_bfloat162*>(hi) = __halves2bfloat162(hx, hy);
    *reinterpret_cast<__nv_bfloat162*>(lo) = __halves2bfloat162(__float2bfloat16(lx), __float2bfloat16(ly));
}
__device__ __forceinline__ float sigmoidf_(float x){ return 1.0f / (1.0f + expf(-x)); }

__device__ __forceinline__ void cpasync16(unsigned saddr, const void* g){
    asm volatile("cp.async.cg.shared.global [%0], [%1], 16;" :: "r"(saddr), "l"(g));
}
#define CP_COMMIT() asm volatile("cp.async.commit_group;")
#define CP_WAIT1()  asm volatile("cp.async.wait_group 1;")
#define CP_WAIT0()  asm volatile("cp.async.wait_group 0;")

// sense-reversing grid barrier (all PGRID CTAs resident by construction)
__device__ __forceinline__ void grid_barrier(int* sense){
    __threadfence();
    __syncthreads();
    if (threadIdx.x == 0){
        int target = *sense ^ 1;
        if (atomicAdd(&g_bar_count, 1) == PGRID - 1){
            atomicExch(&g_bar_count, 0);
            __threadfence();
            g_bar_phase = target;
        } else {
            while (g_bar_phase != target) __nanosleep(40);
        }
        *sense = target;
    }
    __syncthreads();
    __threadfence();
}

// ---------------- phase 1: x_proj = inputs @ W_ih^T + b_ih + b_hh ----------------
struct SmemTiles {
    __nv_bfloat16 a_hi[BM * KPAD];
    __nv_bfloat16 a_lo[BM * KPAD];
    __nv_bfloat16 b_hi[BN * KPAD];
    __nv_bfloat16 b_lo[BN * KPAD];
};

__global__ __launch_bounds__(NTHREADS)
void xproj_gemm(const float* __restrict__ Ain, const float* __restrict__ Wg,
                const float* __restrict__ bias_ih, const float* __restrict__ bias_hh)
{
    __shared__ SmemTiles sm;
    const int tid   = threadIdx.x;
    const int lane  = tid & 31;
    const int wid   = tid >> 5;
    const int warp_m = wid >> 2;
    const int warp_n = wid & 3;
    const int m0 = blockIdx.y * BM;
    const int n0 = blockIdx.x * BN;
    const int KDIM = IN_DIM;

    float acc[2][2][4];
    #pragma unroll
    for (int i = 0; i < 2; i++)
        #pragma unroll
        for (int j = 0; j < 2; j++)
            #pragma unroll
            for (int k = 0; k < 4; k++) acc[i][j][k] = 0.0f;

    const int KITERS = KDIM / BKK;
    int lr[2], lc[2];
    size_t arowoff[2], browoff[2];
    #pragma unroll
    for (int i = 0; i < 2; i++){
        int idx = tid + i * NTHREADS;
        lr[i] = idx >> 3;
        lc[i] = (idx & 7) << 2;
        arowoff[i] = (size_t)(m0 + lr[i]) * KDIM;
        int g = n0 + lr[i];
        browoff[i] = (size_t)((g & 3) * HID + (g >> 2)) * KDIM;
    }

    float4 pa[2], pb[2];
    #pragma unroll
    for (int i = 0; i < 2; i++){
        pa[i] = *reinterpret_cast<const float4*>(Ain + arowoff[i] + lc[i]);
        pb[i] = *reinterpret_cast<const float4*>(Wg  + browoff[i] + lc[i]);
    }

    for (int kt = 0; kt < KITERS; kt++){
        #pragma unroll
        for (int i = 0; i < 2; i++){
            int base = lr[i] * KPAD + lc[i];
            split_pair(pa[i].x, pa[i].y, &sm.a_hi[base],     &sm.a_lo[base]);
            split_pair(pa[i].z, pa[i].w, &sm.a_hi[base + 2], &sm.a_lo[base + 2]);
            split_pair(pb[i].x, pb[i].y, &sm.b_hi[base],     &sm.b_lo[base]);
            split_pair(pb[i].z, pb[i].w, &sm.b_hi[base + 2], &sm.b_lo[base + 2]);
        }
        __syncthreads();

        if (kt + 1 < KITERS){
            int k0 = (kt + 1) * BKK;
            #pragma unroll
            for (int i = 0; i < 2; i++){
                pa[i] = *reinterpret_cast<const float4*>(Ain + arowoff[i] + k0 + lc[i]);
                pb[i] = *reinterpret_cast<const float4*>(Wg  + browoff[i] + k0 + lc[i]);
            }
        }

        #pragma unroll
        for (int kk = 0; kk < 2; kk++){
            const int lrow = lane & 15;
            const int lcol = kk * 16 + ((lane >> 4) << 3);
            unsigned ah[2][4], al[2][4];
            #pragma unroll
            for (int mt = 0; mt < 2; mt++){
                int r = warp_m * 32 + mt * 16 + lrow;
                ldmx4(ah[mt], su32(&sm.a_hi[r * KPAD + lcol]));
                ldmx4(al[mt], su32(&sm.a_lo[r * KPAD + lcol]));
            }
            unsigned bh[2][2], bl[2][2];
            {
                int r = warp_n * 16 + lrow;
                unsigned t4[4];
                ldmx4(t4, su32(&sm.b_hi[r * KPAD + lcol]));
                bh[0][0] = t4[0]; bh[1][0] = t4[1]; bh[0][1] = t4[2]; bh[1][1] = t4[3];
                ldmx4(t4, su32(&sm.b_lo[r * KPAD + lcol]));
                bl[0][0] = t4[0]; bl[1][0] = t4[1]; bl[0][1] = t4[2]; bl[1][1] = t4[3];
            }
            #pragma unroll
            for (int mt = 0; mt < 2; mt++)
                #pragma unroll
                for (int nt = 0; nt < 2; nt++){
                    mma_bf16(acc[mt][nt], ah[mt], bh[nt]);
                    mma_bf16(acc[mt][nt], al[mt], bh[nt]);
                    mma_bf16(acc[mt][nt], ah[mt], bl[nt]);
                }
        }
        __syncthreads();
    }

    #pragma unroll
    for (int mt = 0; mt < 2; mt++)
        #pragma unroll
        for (int nt = 0; nt < 2; nt++)
            #pragma unroll
            for (int pp = 0; pp < 2; pp++){
                int row = m0 + warp_m * 32 + mt * 16 + (lane >> 2) + 8 * pp;
                int col = n0 + warp_n * 16 + nt * 8 + 2 * (lane & 3);
                int r0 = (col & 3) * HID + (col >> 2);
                int r1 = ((col + 1) & 3) * HID + ((col + 1) >> 2);
                float* dst = &g_xp[(size_t)row * GDIM + col];
                dst[0] = acc[mt][nt][2 * pp]     + bias_ih[r0] + bias_hh[r0];
                dst[1] = acc[mt][nt][2 * pp + 1] + bias_ih[r1] + bias_hh[r1];
            }
}

// ---------------- persistent recurrence kernel ----------------
__device__ __forceinline__ void load_chunk(char* smbase, int b, int kt, int s, int tid){
    const __nv_bfloat16* hh = g_hhi[s & 1];
    const __nv_bfloat16* hl = g_hlo[s & 1];
    char* ahi = smbase + OFF_AHI + b * ABUF_B;
    char* alo = smbase + OFF_ALO + b * ABUF_B;
    #pragma unroll
    for (int j = 0; j < 4; j++){
        int c   = tid + j * PTHREADS;   // 0..1023 : 16B chunk id
        int row = c >> 3;
        int cc  = c & 7;
        const __nv_bfloat16* gh = hh + (size_t)row * HID + kt * PBK + cc * 8;
        const __nv_bfloat16* gl = hl + (size_t)row * HID + kt * PBK + cc * 8;
        cpasync16(su32(ahi + row * (APAD * 2) + cc * 16), gh);
        cpasync16(su32(alo + row * (APAD * 2) + cc * 16), gl);
    }
}

__global__ __launch_bounds__(PTHREADS, 1)
void lstm_persistent(const float* __restrict__ W_hh)
{
    extern __shared__ char smbase[];
    const int tid  = threadIdx.x;
    const int lane = tid & 31;
    const int wid  = tid >> 5;
    const int warp_m = wid >> 1;   // 0..3 (32 rows each)
    const int warp_n = wid & 1;    // 0..1 (16 cols each)
    const int n0 = blockIdx.x * PBN;

    __nv_bfloat16* w_hi = (__nv_bfloat16*)(smbase + OFF_WHI);
    __nv_bfloat16* w_lo = (__nv_bfloat16*)(smbase + OFF_WLO);

    // one-time: gather + split this CTA's W_hh slice into SMEM
    for (int idx = tid; idx < PBN * (HID / 4); idx += PTHREADS){
        int j  = idx >> 8;     // 0..31 slice row (interleaved gate col)
        int k4 = idx & 255;
        int g  = n0 + j;
        const float4 v = *reinterpret_cast<const float4*>(
            W_hh + (size_t)((g & 3) * HID + (g >> 2)) * HID + k4 * 4);
        int base = j * WPAD + k4 * 4;
        split_pair(v.x, v.y, &w_hi[base],     &w_lo[base]);
        split_pair(v.z, v.w, &w_hi[base + 2], &w_lo[base + 2]);
    }
    __syncthreads();

    int sense = 0;
    for (int s = 0; s < S_LEN; s++){
        float acc[2][2][4];
        #pragma unroll
        for (int i = 0; i < 2; i++)
            #pragma unroll
            for (int j = 0; j < 2; j++)
                #pragma unroll
                for (int k = 0; k < 4; k++) acc[i][j][k] = 0.0f;

        load_chunk(smbase, 0, 0, s, tid);
        CP_COMMIT();

        for (int kt = 0; kt < PKITERS; kt++){
            if (kt + 1 < PKITERS){
                load_chunk(smbase, (kt + 1) & 1, kt + 1, s, tid);
                CP_COMMIT();
                CP_WAIT1();
            } else {
                CP_WAIT0();
            }
            __syncthreads();

            const __nv_bfloat16* ah_t = (const __nv_bfloat16*)(smbase + OFF_AHI + (kt & 1) * ABUF_B);
            const __nv_bfloat16* al_t = (const __nv_bfloat16*)(smbase + OFF_ALO + (kt & 1) * ABUF_B);

            #pragma unroll
            for (int kk = 0; kk < PBK / 16; kk++){
                const int lrow = lane & 15;
                const int lcol = kk * 16 + ((lane >> 4) << 3);
                unsigned ah[2][4], al[2][4];
                #pragma unroll
                for (int mt = 0; mt < 2; mt++){
                    int r = warp_m * 32 + mt * 16 + lrow;
                    ldmx4(ah[mt], su32(&ah_t[r * APAD + lcol]));
                    ldmx4(al[mt], su32(&al_t[r * APAD + lcol]));
                }
                unsigned bh[2][2], bl[2][2];
                {
                    int r = warp_n * 16 + lrow;
                    unsigned t4[4];
                    ldmx4(t4, su32(&w_hi[r * WPAD + kt * PBK + lcol]));
                    bh[0][0] = t4[0]; bh[1][0] = t4[1]; bh[0][1] = t4[2]; bh[1][1] = t4[3];
                    ldmx4(t4, su32(&w_lo[r * WPAD + kt * PBK + lcol]));
                    bl[0][0] = t4[0]; bl[1][0] = t4[1]; bl[0][1] = t4[2]; bl[1][1] = t4[3];
                }
                #pragma unroll
                for (int mt = 0; mt < 2; mt++)
                    #pragma unroll
                    for (int nt = 0; nt < 2; nt++){
                        mma_bf16(acc[mt][nt], ah[mt], bh[nt]);
                        mma_bf16(acc[mt][nt], al[mt], bh[nt]);
                        mma_bf16(acc[mt][nt], ah[mt], bl[nt]);
                    }
            }
            __syncthreads();   // compute done before next chunk overwrites buffer
        }

        // ---- epilogue: stage gates, fused LSTM elementwise ----
        float* gates = (float*)(smbase + OFF_GATES);
        #pragma unroll
        for (int mt = 0; mt < 2; mt++)
            #pragma unroll
            for (int nt = 0; nt < 2; nt++)
                #pragma unroll
                for (int pp = 0; pp < 2; pp++){
                    int row = warp_m * 32 + mt * 16 + (lane >> 2) + 8 * pp;
                    int col = warp_n * 16 + nt * 8 + 2 * (lane & 3);
                    gates[row * PBN + col]     = acc[mt][nt][2 * pp];
                    gates[row * PBN + col + 1] = acc[mt][nt][2 * pp + 1];
                }
        __syncthreads();

        __nv_bfloat16* hh_n = g_hhi[(s + 1) & 1];
        __nv_bfloat16* hl_n = g_hlo[(s + 1) & 1];
        const float* xpbase = &g_xp[(size_t)((size_t)s * NBATCH) * GDIM + n0];
        for (int i = tid; i < NBATCH * (PBN / 4); i += PTHREADS){
            int m = i >> 3;        // batch row
            int u = i & 7;         // unit within CTA slice
            float4 gv = *reinterpret_cast<float4*>(&gates[m * PBN + u * 4]);
            float4 xv = *reinterpret_cast<const float4*>(xpbase + (size_t)m * GDIM + u * 4);
            float ig = sigmoidf_(gv.x + xv.x);
            float fg = sigmoidf_(gv.y + xv.y);
            float gg = tanhf(gv.z + xv.z);
            float og = sigmoidf_(gv.w + xv.w);
            int hidx = m * HID + (n0 >> 2) + u;
            float cn = fg * g_cbuf[hidx] + ig * gg;
            g_cbuf[hidx] = cn;
            float hv = og * tanhf(cn);
            __nv_bfloat16 hb = __float2bfloat16(hv);
            hh_n[hidx] = hb;
            hl_n[hidx] = __float2bfloat16(hv - __bfloat162float(hb));
        }

        grid_barrier(&sense);
    }
}

// ---------------- small kernels ----------------
__global__ void init_state(const float* __restrict__ h0, const float* __restrict__ c0){
    int i = blockIdx.x * blockDim.x + threadIdx.x;
    if (i < NBATCH * HID){
        float hv = h0[i];
        __nv_bfloat16 hb = __float2bfloat16(hv);
        g_hhi[0][i] = hb;
        g_hlo[0][i] = __float2bfloat16(hv - __bfloat162float(hb));
        g_cbuf[i]   = c0[i];
    }
    if (i == 0){ g_bar_count = 0; g_bar_phase = 0; }
}

__global__ void lstm_decode(const float* __restrict__ W_dec, const float* __restrict__ b_dec,
                            float* __restrict__ out){
    __shared__ float wsh[NOUT * HID];
    __shared__ float lsh[NOUT * NBATCH];
    __shared__ float red[2 * NOUT];
    for (int i = threadIdx.x; i < NOUT * HID; i += blockDim.x) wsh[i] = W_dec[i];
    __syncthreads();
    int b = threadIdx.x;   // 128 threads, one per batch row
    float a0 = b_dec[0], a1 = b_dec[1], a2 = b_dec[2], a3 = b_dec[3];
    const __nv_bfloat16* hi = &g_hhi[0][b * HID];   // after 512 steps h is in buffer 0
    const __nv_bfloat16* lo = &g_hlo[0][b * HID];
    for (int h = 0; h < HID; h++){
        float hv = __bfloat162float(hi[h]) + __bfloat162float(lo[h]);
        a0 += hv * wsh[h];
        a1 += hv * wsh[HID + h];
        a2 += hv * wsh[2 * HID + h];
        a3 += hv * wsh[3 * HID + h];
    }
    lsh[0 * NBATCH + b] = a0; lsh[1 * NBATCH + b] = a1;
    lsh[2 * NBATCH + b] = a2; lsh[3 * NBATCH + b] = a3;
    __syncthreads();
    if (threadIdx.x < NOUT){
        int o = threadIdx.x;
        float m = -1e30f;
        for (int j = 0; j < NBATCH; j++) m = fmaxf(m, lsh[o * NBATCH + j]);
        float sum = 0.0f;
        for (int j = 0; j < NBATCH; j++) sum += expf(lsh[o * NBATCH + j] - m);
        red[o] = m; red[NOUT + o] = sum;
    }
    __syncthreads();
    #pragma unroll
    for (int o = 0; o < NOUT; o++)
        out[b * NOUT + o] = expf(lsh[o * NBATCH + b] - red[o]) / red[NOUT + o];
}

// ---------------- launch ----------------
extern "C" void kernel_launch(void* const* d_in, const int* in_sizes, int n_in,
                              void* d_out, int out_size)
{
    const float* inputs = (const float*)d_in[0];
    const float* h0     = (const float*)d_in[1];
    const float* c0     = (const float*)d_in[2];
    const float* W_ih   = (const float*)d_in[3];
    const float* W_hh   = (const float*)d_in[4];
    const float* b_ih   = (const float*)d_in[5];
    const float* b_hh   = (const float*)d_in[6];
    const float* W_dec  = (const float*)d_in[7];
    const float* b_dec  = (const float*)d_in[8];
    float* out = (float*)d_out;

    cudaFuncSetAttribute(lstm_persistent,
                         cudaFuncAttributeMaxDynamicSharedMemorySize, PSMEM_TOTAL);

    init_state<<<(NBATCH * HID + 255) / 256, 256>>>(h0, c0);

    // Phase 1: x_proj for all timesteps (M=65536, N=4096, K=512)
    dim3 g1(GDIM / BN, (S_LEN * NBATCH) / BM);
    xproj_gemm<<<g1, NTHREADS>>>(inputs, W_ih, b_ih, b_hh);

    // Recurrence: one persistent kernel, 512 internally-synchronized steps
    lstm_persistent<<<PGRID, PTHREADS, PSMEM_TOTAL>>>(W_hh);

    lstm_decode<<<1, 128>>>(W_dec, b_dec, out);
}

// round 5
// speedup vs baseline: 1.1983x; 1.1836x over previous
#include <cuda_runtime.h>
#include <cuda_bf16.h>
#include <cuda_fp16.h>
#include <math.h>
#include <stdint.h>

#define S_LEN   512
#define NBATCH  128
#define IN_DIM  512
#define HID     1024
#define GDIM    4096   // interleaved: col g -> gate g&3, unit g>>2
#define NOUT    4

// phase-1 tiling (proven R2 kernel)
#define BM 64
#define BN 64
#define BKK 32
#define KPAD 40
#define NTHREADS 256

// recurrence (persistent, SIMT mma, fp16 2-pass)
#define PBN 32
#define PGRID (GDIM / PBN)        // 128 CTAs, all resident
#define PTH 512                   // 16 warps
#define NCH 16                    // K chunks of 64
#define WSTR 1032                 // W smem row stride (fp16 elems): +16B/row mod 128
#define APAD 72                   // h chunk row stride (fp16 elems)
#define OFF_W 0
#define WBYTES (PBN * WSTR * 2)   // 66048
#define ABUF_P (NBATCH * APAD * 2)  // 18432 bytes per part
#define SSTR (2 * ABUF_P)         // stage stride (hi+lo) = 36864
#define OFF_A WBYTES
#define DYN_B (OFF_A + 2 * SSTR)  // 139776

__device__ float g_xp[(size_t)S_LEN * NBATCH * GDIM];
__device__ __half g_hh[2][NBATCH * HID];
__device__ __half g_hl[2][NBATCH * HID];
__device__ int g_bar_count;
__device__ volatile int g_bar_phase;

__device__ __forceinline__ unsigned su32(const void* p){
    return (unsigned)__cvta_generic_to_shared(p);
}
__device__ __forceinline__ float sigmoidf_(float x){ return 1.0f / (1.0f + expf(-x)); }
__device__ __forceinline__ void cpasync16(unsigned saddr, const void* g){
    asm volatile("cp.async.cg.shared.global [%0], [%1], 16;" :: "r"(saddr), "l"(g));
}
#define CP_COMMIT() asm volatile("cp.async.commit_group;")
#define CP_WAIT(n)  asm volatile("cp.async.wait_group %0;" :: "n"(n))

__device__ __forceinline__ void ldmx4(unsigned* r, unsigned addr){
    asm volatile("ldmatrix.sync.aligned.m8n8.x4.shared.b16 {%0,%1,%2,%3}, [%4];"
        : "=r"(r[0]), "=r"(r[1]), "=r"(r[2]), "=r"(r[3]) : "r"(addr));
}
__device__ __forceinline__ void mma_bf16(float* d, const unsigned* a, const unsigned* b){
    asm volatile("mma.sync.aligned.m16n8k16.row.col.f32.bf16.bf16.f32 "
        "{%0,%1,%2,%3},{%4,%5,%6,%7},{%8,%9},{%0,%1,%2,%3};"
        : "+f"(d[0]), "+f"(d[1]), "+f"(d[2]), "+f"(d[3])
        : "r"(a[0]), "r"(a[1]), "r"(a[2]), "r"(a[3]), "r"(b[0]), "r"(b[1]));
}
__device__ __forceinline__ void mma_f16(float* d, const unsigned* a, const unsigned* b){
    asm volatile("mma.sync.aligned.m16n8k16.row.col.f32.f16.f16.f32 "
        "{%0,%1,%2,%3},{%4,%5,%6,%7},{%8,%9},{%0,%1,%2,%3};"
        : "+f"(d[0]), "+f"(d[1]), "+f"(d[2]), "+f"(d[3])
        : "r"(a[0]), "r"(a[1]), "r"(a[2]), "r"(a[3]), "r"(b[0]), "r"(b[1]));
}
__device__ __forceinline__ void split_pair(float x, float y, __nv_bfloat16* hi, __nv_bfloat16* lo){
    __nv_bfloat16 hx = __float2bfloat16(x);
    __nv_bfloat16 hy = __float2bfloat16(y);
    float lx = x - __bfloat162float(hx);
    float ly = y - __bfloat162float(hy);
    *reinterpret_cast<__nv_bfloat162*>(hi) = __halves2bfloat162(hx, hy);
    *reinterpret_cast<__nv_bfloat162*>(lo) = __halves2bfloat162(__float2bfloat16(lx), __float2bfloat16(ly));
}

__device__ __forceinline__ void grid_barrier(int* sense){
    __threadfence();
    __syncthreads();
    if (threadIdx.x == 0){
        int target = *sense ^ 1;
        if (atomicAdd(&g_bar_count, 1) == PGRID - 1){
            atomicExch(&g_bar_count, 0);
            __threadfence();
            g_bar_phase = target;
        } else {
            while (g_bar_phase != target) __nanosleep(40);
        }
        *sense = target;
    }
    __syncthreads();
    __threadfence();
}

// ---------------- phase 1 (unchanged, proven) ----------------
struct SmemTiles {
    __nv_bfloat16 a_hi[BM * KPAD];
    __nv_bfloat16 a_lo[BM * KPAD];
    __nv_bfloat16 b_hi[BN * KPAD];
    __nv_bfloat16 b_lo[BN * KPAD];
};

__global__ __launch_bounds__(NTHREADS)
void xproj_gemm(const float* __restrict__ Ain, const float* __restrict__ Wg,
                const float* __restrict__ bias_ih, const float* __restrict__ bias_hh)
{
    __shared__ SmemTiles sm;
    const int tid = threadIdx.x, lane = tid & 31, wid = tid >> 5;
    const int warp_m = wid >> 2, warp_n = wid & 3;
    const int m0 = blockIdx.y * BM, n0 = blockIdx.x * BN;
    const int KDIM = IN_DIM;

    float acc[2][2][4];
    #pragma unroll
    for (int i = 0; i < 2; i++)
        #pragma unroll
        for (int j = 0; j < 2; j++)
            #pragma unroll
            for (int k = 0; k < 4; k++) acc[i][j][k] = 0.0f;

    const int KITERS = KDIM / BKK;
    int lr[2], lc[2];
    size_t arowoff[2], browoff[2];
    #pragma unroll
    for (int i = 0; i < 2; i++){
        int idx = tid + i * NTHREADS;
        lr[i] = idx >> 3;
        lc[i] = (idx & 7) << 2;
        arowoff[i] = (size_t)(m0 + lr[i]) * KDIM;
        int g = n0 + lr[i];
        browoff[i] = (size_t)((g & 3) * HID + (g >> 2)) * KDIM;
    }
    float4 pa[2], pb[2];
    #pragma unroll
    for (int i = 0; i < 2; i++){
        pa[i] = *reinterpret_cast<const float4*>(Ain + arowoff[i] + lc[i]);
        pb[i] = *reinterpret_cast<const float4*>(Wg  + browoff[i] + lc[i]);
    }

    for (int kt = 0; kt < KITERS; kt++){
        #pragma unroll
        for (int i = 0; i < 2; i++){
            int base = lr[i] * KPAD + lc[i];
            split_pair(pa[i].x, pa[i].y, &sm.a_hi[base],     &sm.a_lo[base]);
            split_pair(pa[i].z, pa[i].w, &sm.a_hi[base + 2], &sm.a_lo[base + 2]);
            split_pair(pb[i].x, pb[i].y, &sm.b_hi[base],     &sm.b_lo[base]);
            split_pair(pb[i].z, pb[i].w, &sm.b_hi[base + 2], &sm.b_lo[base + 2]);
        }
        __syncthreads();
        if (kt + 1 < KITERS){
            int k0 = (kt + 1) * BKK;
            #pragma unroll
            for (int i = 0; i < 2; i++){
                pa[i] = *reinterpret_cast<const float4*>(Ain + arowoff[i] + k0 + lc[i]);
                pb[i] = *reinterpret_cast<const float4*>(Wg  + browoff[i] + k0 + lc[i]);
            }
        }
        #pragma unroll
        for (int kk = 0; kk < 2; kk++){
            const int lrow = lane & 15;
            const int lcol = kk * 16 + ((lane >> 4) << 3);
            unsigned ah[2][4], al[2][4];
            #pragma unroll
            for (int mt = 0; mt < 2; mt++){
                int r = warp_m * 32 + mt * 16 + lrow;
                ldmx4(ah[mt], su32(&sm.a_hi[r * KPAD + lcol]));
                ldmx4(al[mt], su32(&sm.a_lo[r * KPAD + lcol]));
            }
            unsigned bh[2][2], bl[2][2];
            {
                int r = warp_n * 16 + lrow;
                unsigned t4[4];
                ldmx4(t4, su32(&sm.b_hi[r * KPAD + lcol]));
                bh[0][0] = t4[0]; bh[1][0] = t4[1]; bh[0][1] = t4[2]; bh[1][1] = t4[3];
                ldmx4(t4, su32(&sm.b_lo[r * KPAD + lcol]));
                bl[0][0] = t4[0]; bl[1][0] = t4[1]; bl[0][1] = t4[2]; bl[1][1] = t4[3];
            }
            #pragma unroll
            for (int mt = 0; mt < 2; mt++)
                #pragma unroll
                for (int nt = 0; nt < 2; nt++){
                    mma_bf16(acc[mt][nt], ah[mt], bh[nt]);
                    mma_bf16(acc[mt][nt], al[mt], bh[nt]);
                    mma_bf16(acc[mt][nt], ah[mt], bl[nt]);
                }
        }
        __syncthreads();
    }

    #pragma unroll
    for (int mt = 0; mt < 2; mt++)
        #pragma unroll
        for (int nt = 0; nt < 2; nt++)
            #pragma unroll
            for (int pp = 0; pp < 2; pp++){
                int row = m0 + warp_m * 32 + mt * 16 + (lane >> 2) + 8 * pp;
                int col = n0 + warp_n * 16 + nt * 8 + 2 * (lane & 3);
                int r0 = (col & 3) * HID + (col >> 2);
                int r1 = ((col + 1) & 3) * HID + ((col + 1) >> 2);
                float* dst = &g_xp[(size_t)row * GDIM + col];
                dst[0] = acc[mt][nt][2 * pp]     + bias_ih[r0] + bias_hh[r0];
                dst[1] = acc[mt][nt][2 * pp + 1] + bias_ih[r1] + bias_hh[r1];
            }
}

// ---------------- persistent recurrence (16 warps, fp16 2-pass) ----------------
__device__ __forceinline__ void load_chunk(char* dyn, int st, int kt,
                                           const __half* hh, const __half* hl, int tid){
    char* base = dyn + OFF_A + st * SSTR;
    #pragma unroll
    for (int i = 0; i < 4; i++){
        int u = tid + i * PTH;      // 0..2047 16B-chunk id
        int part = u >> 10;         // 0 hi, 1 lo
        int w = u & 1023;
        int r = w >> 3, b = w & 7;
        const __half* src = (part ? hl : hh) + (size_t)r * HID + kt * 64 + b * 8;
        cpasync16(su32(base + part * ABUF_P + r * (APAD * 2) + b * 16), src);
    }
}

__global__ __launch_bounds__(PTH, 1)
void lstm_rec(const float* __restrict__ W_hh, const float* __restrict__ c0)
{
    extern __shared__ __align__(128) char dyn[];
    const int tid  = threadIdx.x;
    const int lane = tid & 31;
    const int wid  = tid >> 5;
    const int warp_m = wid >> 1;    // 0..7, 16 rows each
    const int warp_n = wid & 1;     // 0..1, 16 cols each
    const int n0 = blockIdx.x * PBN;

    __half* w_sm = (__half*)(dyn + OFF_W);

    // one-time: gather W_hh slice (interleaved gate cols) -> fp16 smem
    for (int idx = tid; idx < PBN * (HID / 4); idx += PTH){
        int j = idx >> 8;              // 0..31
        int c = (idx & 255) * 4;
        int g = n0 + j;
        const float4 v = *reinterpret_cast<const float4*>(
            W_hh + (size_t)((g & 3) * HID + (g >> 2)) * HID + c);
        *reinterpret_cast<__half2*>(&w_sm[j * WSTR + c])     = __floats2half2_rn(v.x, v.y);
        *reinterpret_cast<__half2*>(&w_sm[j * WSTR + c + 2]) = __floats2half2_rn(v.z, v.w);
    }

    // register-resident cell state: 2 units per thread
    const int erow = tid >> 2;                 // batch row
    const int q    = tid & 3;                  // quarter of CTA cols
    const int ub   = (n0 >> 2);                // global unit base for CTA
    float creg0 = c0[erow * HID + ub + q * 2];
    float creg1 = c0[erow * HID + ub + q * 2 + 1];
    __syncthreads();

    int sense = 0;
    for (int s = 0; s < S_LEN; s++){
        const __half* hh = g_hh[s & 1];
        const __half* hl = g_hl[s & 1];

        float acc[2][4];
        #pragma unroll
        for (int j = 0; j < 2; j++)
            #pragma unroll
            for (int k = 0; k < 4; k++) acc[j][k] = 0.0f;

        load_chunk(dyn, 0, 0, hh, hl, tid);
        CP_COMMIT();

        for (int kt = 0; kt < NCH; kt++){
            if (kt + 1 < NCH){
                load_chunk(dyn, (kt + 1) & 1, kt + 1, hh, hl, tid);
                CP_COMMIT();
                CP_WAIT(1);
            } else {
                CP_WAIT(0);
            }
            __syncthreads();

            const __half* ah_t = (const __half*)(dyn + OFF_A + (kt & 1) * SSTR);
            const __half* al_t = (const __half*)(dyn + OFF_A + (kt & 1) * SSTR + ABUF_P);

            #pragma unroll
            for (int kk = 0; kk < 4; kk++){
                const int lrow = lane & 15;
                const int lcol = kk * 16 + ((lane >> 4) << 3);
                unsigned ah[4], al[4];
                int ar = warp_m * 16 + lrow;
                ldmx4(ah, su32(&ah_t[ar * APAD + lcol]));
                ldmx4(al, su32(&al_t[ar * APAD + lcol]));
                unsigned b[2][2];
                {
                    int r = warp_n * 16 + lrow;
                    unsigned t4[4];
                    ldmx4(t4, su32(&w_sm[r * WSTR + kt * 64 + lcol]));
                    b[0][0] = t4[0]; b[1][0] = t4[1]; b[0][1] = t4[2]; b[1][1] = t4[3];
                }
                #pragma unroll
                for (int nt = 0; nt < 2; nt++){
                    mma_f16(acc[nt], ah, b[nt]);
                    mma_f16(acc[nt], al, b[nt]);
                }
            }
            __syncthreads();   // compute done before buffer reuse
        }

        // stage gates in smem (reuse chunk stage 0 region)
        float* gates = (float*)(dyn + OFF_A);
        #pragma unroll
        for (int nt = 0; nt < 2; nt++)
            #pragma unroll
            for (int pp = 0; pp < 2; pp++){
                int row = warp_m * 16 + (lane >> 2) + 8 * pp;
                int col = warp_n * 16 + nt * 8 + 2 * (lane & 3);
                gates[row * PBN + col]     = acc[nt][2 * pp];
                gates[row * PBN + col + 1] = acc[nt][2 * pp + 1];
            }
        __syncthreads();

        // fused LSTM elementwise: 2 units per thread, c in registers
        {
            const float* xpr = g_xp + ((size_t)s * NBATCH + erow) * GDIM + n0 + q * 8;
            float4 x0 = *reinterpret_cast<const float4*>(xpr);
            float4 x1 = *reinterpret_cast<const float4*>(xpr + 4);
            const float* gr = &gates[erow * PBN + q * 8];
            float4 g0 = *reinterpret_cast<const float4*>(gr);
            float4 g1 = *reinterpret_cast<const float4*>(gr + 4);

            float ig = sigmoidf_(g0.x + x0.x);
            float fg = sigmoidf_(g0.y + x0.y);
            float gg = tanhf    (g0.z + x0.z);
            float og = sigmoidf_(g0.w + x0.w);
            creg0 = fg * creg0 + ig * gg;
            float hv0 = og * tanhf(creg0);

            ig = sigmoidf_(g1.x + x1.x);
            fg = sigmoidf_(g1.y + x1.y);
            gg = tanhf    (g1.z + x1.z);
            og = sigmoidf_(g1.w + x1.w);
            creg1 = fg * creg1 + ig * gg;
            float hv1 = og * tanhf(creg1);

            __half h0 = __float2half_rn(hv0);
            __half h1 = __float2half_rn(hv1);
            __half l0 = __float2half_rn(hv0 - __half2float(h0));
            __half l1 = __float2half_rn(hv1 - __half2float(h1));

            int hidx = erow * HID + ub + q * 2;
            *reinterpret_cast<__half2*>(&g_hh[(s + 1) & 1][hidx]) = __halves2half2(h0, h1);
            *reinterpret_cast<__half2*>(&g_hl[(s + 1) & 1][hidx]) = __halves2half2(l0, l1);
        }

        grid_barrier(&sense);
    }
}

// ---------------- small kernels ----------------
__global__ void init_state(const float* __restrict__ h0){
    int i = blockIdx.x * blockDim.x + threadIdx.x;
    if (i < NBATCH * HID){
        float hv = h0[i];
        __half hb = __float2half_rn(hv);
        g_hh[0][i] = hb;
        g_hl[0][i] = __float2half_rn(hv - __half2float(hb));
    }
    if (i == 0){ g_bar_count = 0; g_bar_phase = 0; }
}

__global__ void lstm_decode(const float* __restrict__ W_dec, const float* __restrict__ b_dec,
                            float* __restrict__ out){
    __shared__ float wsh[NOUT * HID];
    __shared__ float lsh[NOUT * NBATCH];
    __shared__ float red[2 * NOUT];
    int tid = threadIdx.x;
    for (int i = tid; i < NOUT * HID; i += 512) wsh[i] = W_dec[i];
    __syncthreads();
    int b = tid >> 2, q = tid & 3;
    const __half* hi = &g_hh[0][b * HID + q * 256];
    const __half* lo = &g_hl[0][b * HID + q * 256];
    float a[4] = {0.f, 0.f, 0.f, 0.f};
    for (int k = 0; k < 256; k++){
        float hv = __half2float(hi[k]) + __half2float(lo[k]);
        int kk = q * 256 + k;
        a[0] += hv * wsh[kk];
        a[1] += hv * wsh[HID + kk];
        a[2] += hv * wsh[2 * HID + kk];
        a[3] += hv * wsh[3 * HID + kk];
    }
    #pragma unroll
    for (int o = 0; o < 4; o++){
        a[o] += __shfl_xor_sync(0xFFFFFFFFu, a[o], 1);
        a[o] += __shfl_xor_sync(0xFFFFFFFFu, a[o], 2);
    }
    if (q == 0){
        #pragma unroll
        for (int o = 0; o < 4; o++) lsh[o * NBATCH + b] = a[o] + b_dec[o];
    }
    __syncthreads();
    if (tid < NOUT){
        int o = tid;
        float m = -1e30f;
        for (int j = 0; j < NBATCH; j++) m = fmaxf(m, lsh[o * NBATCH + j]);
        float sum = 0.0f;
        for (int j = 0; j < NBATCH; j++) sum += expf(lsh[o * NBATCH + j] - m);
        red[o] = m; red[NOUT + o] = sum;
    }
    __syncthreads();
    if (tid < NBATCH){
        #pragma unroll
        for (int o = 0; o < NOUT; o++)
            out[tid * NOUT + o] = expf(lsh[o * NBATCH + tid] - red[o]) / red[NOUT + o];
    }
}

// ---------------- launch ----------------
extern "C" void kernel_launch(void* const* d_in, const int* in_sizes, int n_in,
                              void* d_out, int out_size)
{
    const float* inputs = (const float*)d_in[0];
    const float* h0     = (const float*)d_in[1];
    const float* c0     = (const float*)d_in[2];
    const float* W_ih   = (const float*)d_in[3];
    const float* W_hh   = (const float*)d_in[4];
    const float* b_ih   = (const float*)d_in[5];
    const float* b_hh   = (const float*)d_in[6];
    const float* W_dec  = (const float*)d_in[7];
    const float* b_dec  = (const float*)d_in[8];
    float* out = (float*)d_out;

    cudaFuncSetAttribute(lstm_rec, cudaFuncAttributeMaxDynamicSharedMemorySize, DYN_B);

    init_state<<<(NBATCH * HID + 255) / 256, 256>>>(h0);

    dim3 g1(GDIM / BN, (S_LEN * NBATCH) / BM);
    xproj_gemm<<<g1, NTHREADS>>>(inputs, W_ih, b_ih, b_hh);

    lstm_rec<<<PGRID, PTH, DYN_B>>>(W_hh, c0);

    lstm_decode<<<1, 512>>>(W_dec, b_dec, out);
}

// round 6
// speedup vs baseline: 1.6934x; 1.4131x over previous
#include <cuda_runtime.h>
#include <cuda_bf16.h>
#include <cuda_fp16.h>
#include <math.h>
#include <stdint.h>

#define S_LEN   512
#define NBATCH  128
#define IN_DIM  512
#define HID     1024
#define GDIM    4096   // interleaved: col g -> gate g&3, unit g>>2
#define NOUT    4

// phase-1 tiling
#define BM 64
#define BN 64
#define BKK 32
#define KPAD 40        // fp16 elems; 80B rows -> ldmatrix conflict-free
#define NTHREADS 256

// recurrence
#define PBN 64
#define PGRID (GDIM / PBN)       // 64 CTAs
#define PTH 512                  // 16 warps
#define NCH 8                    // K chunks of 128
#define CHB 32768                // chunk bytes: 128 rows x 256B
#define WB  131072               // W: 64 rows x 2048B
#define OFF_W 0
#define OFF_A WB
#define DYN_B (WB + 3 * CHB)     // 229376 <= 232448

__device__ float  g_xp[(size_t)S_LEN * NBATCH * GDIM];   // x_proj (+bias), fp32
__device__ __half g_xh[(size_t)S_LEN * NBATCH * IN_DIM]; // inputs fp16
__device__ __half g_wih[(size_t)GDIM * IN_DIM];          // gathered W_ih fp16
__device__ float  g_bias[GDIM];                          // gathered b_ih+b_hh
__device__ __half g_hh[2][NBATCH * HID];                 // hidden fp16, dbl-buffered
__device__ int g_bar_count;
__device__ volatile int g_bar_phase;

__device__ __forceinline__ unsigned su32(const void* p){
    return (unsigned)__cvta_generic_to_shared(p);
}
__device__ __forceinline__ float sigmoidf_(float x){ return 1.0f / (1.0f + expf(-x)); }
__device__ __forceinline__ void cpasync16(unsigned saddr, const void* g){
    asm volatile("cp.async.cg.shared.global [%0], [%1], 16;" :: "r"(saddr), "l"(g));
}
#define CP_COMMIT() asm volatile("cp.async.commit_group;")
#define CP_WAIT(n)  asm volatile("cp.async.wait_group %0;" :: "n"(n))

__device__ __forceinline__ void ldmx4(unsigned* r, unsigned addr){
    asm volatile("ldmatrix.sync.aligned.m8n8.x4.shared.b16 {%0,%1,%2,%3}, [%4];"
        : "=r"(r[0]), "=r"(r[1]), "=r"(r[2]), "=r"(r[3]) : "r"(addr));
}
__device__ __forceinline__ void mma_f16(float* d, const unsigned* a, const unsigned* b){
    asm volatile("mma.sync.aligned.m16n8k16.row.col.f32.f16.f16.f32 "
        "{%0,%1,%2,%3},{%4,%5,%6,%7},{%8,%9},{%0,%1,%2,%3};"
        : "+f"(d[0]), "+f"(d[1]), "+f"(d[2]), "+f"(d[3])
        : "r"(a[0]), "r"(a[1]), "r"(a[2]), "r"(a[3]), "r"(b[0]), "r"(b[1]));
}

__device__ __forceinline__ void grid_barrier(int* sense){
    __threadfence();
    __syncthreads();
    if (threadIdx.x == 0){
        int target = *sense ^ 1;
        if (atomicAdd(&g_bar_count, 1) == PGRID - 1){
            atomicExch(&g_bar_count, 0);
            __threadfence();
            g_bar_phase = target;
        } else {
            while (g_bar_phase != target) __nanosleep(40);
        }
        *sense = target;
    }
    __syncthreads();
    __threadfence();
}

// ---------------- conversion pre-kernels ----------------
__global__ void cvt_inputs(const float* __restrict__ in){
    size_t i = (size_t)(blockIdx.x * blockDim.x + threadIdx.x) * 8;
    if (i < (size_t)S_LEN * NBATCH * IN_DIM){
        float4 v0 = *reinterpret_cast<const float4*>(in + i);
        float4 v1 = *reinterpret_cast<const float4*>(in + i + 4);
        __half2* d = reinterpret_cast<__half2*>(&g_xh[i]);
        d[0] = __floats2half2_rn(v0.x, v0.y);
        d[1] = __floats2half2_rn(v0.z, v0.w);
        d[2] = __floats2half2_rn(v1.x, v1.y);
        d[3] = __floats2half2_rn(v1.z, v1.w);
    }
}
__global__ void cvt_wih(const float* __restrict__ W_ih,
                        const float* __restrict__ b_ih, const float* __restrict__ b_hh,
                        const float* __restrict__ h0){
    int idx = blockIdx.x * blockDim.x + threadIdx.x;   // over GDIM*IN_DIM/4
    if (idx < GDIM * (IN_DIM / 4)){
        int g = idx >> 7;            // IN_DIM/4 = 128
        int c = (idx & 127) * 4;
        int r = (g & 3) * HID + (g >> 2);
        float4 v = *reinterpret_cast<const float4*>(W_ih + (size_t)r * IN_DIM + c);
        __half2* d = reinterpret_cast<__half2*>(&g_wih[(size_t)g * IN_DIM + c]);
        d[0] = __floats2half2_rn(v.x, v.y);
        d[1] = __floats2half2_rn(v.z, v.w);
        if (c == 0) g_bias[g] = b_ih[r] + b_hh[r];
    }
    if (idx < NBATCH * HID) g_hh[0][idx] = __float2half_rn(h0[idx]);
    if (idx == 0){ g_bar_count = 0; g_bar_phase = 0; }
}

// ---------------- phase 1: x_proj (single-pass fp16) ----------------
struct P1Smem {
    __half a[BM * KPAD];
    __half b[BN * KPAD];
};

__global__ __launch_bounds__(NTHREADS)
void xproj_gemm()
{
    __shared__ P1Smem sm;
    const int tid = threadIdx.x, lane = tid & 31, wid = tid >> 5;
    const int warp_m = wid >> 2, warp_n = wid & 3;
    const int m0 = blockIdx.y * BM, n0 = blockIdx.x * BN;

    float acc[2][2][4];
    #pragma unroll
    for (int i = 0; i < 2; i++)
        #pragma unroll
        for (int j = 0; j < 2; j++)
            #pragma unroll
            for (int k = 0; k < 4; k++) acc[i][j][k] = 0.0f;

    // per-thread: one 16B chunk per tile per operand (64 rows x 4 chunks)
    const int lrw = tid >> 2;         // row 0..63
    const int lcc = (tid & 3) * 8;    // col 0..31 step 8
    const __half* asrc = g_xh  + (size_t)(m0 + lrw) * IN_DIM + lcc;
    const __half* bsrc = g_wih + (size_t)(n0 + lrw) * IN_DIM + lcc;

    uint4 pa = *reinterpret_cast<const uint4*>(asrc);
    uint4 pb = *reinterpret_cast<const uint4*>(bsrc);

    const int KITERS = IN_DIM / BKK;
    for (int kt = 0; kt < KITERS; kt++){
        *reinterpret_cast<uint4*>(&sm.a[lrw * KPAD + lcc]) = pa;
        *reinterpret_cast<uint4*>(&sm.b[lrw * KPAD + lcc]) = pb;
        __syncthreads();
        if (kt + 1 < KITERS){
            pa = *reinterpret_cast<const uint4*>(asrc + (kt + 1) * BKK);
            pb = *reinterpret_cast<const uint4*>(bsrc + (kt + 1) * BKK);
        }
        #pragma unroll
        for (int kk = 0; kk < 2; kk++){
            const int lrow = lane & 15;
            const int lcol = kk * 16 + ((lane >> 4) << 3);
            unsigned ah[2][4];
            #pragma unroll
            for (int mt = 0; mt < 2; mt++){
                int r = warp_m * 32 + mt * 16 + lrow;
                ldmx4(ah[mt], su32(&sm.a[r * KPAD + lcol]));
            }
            unsigned b[2][2];
            {
                int r = warp_n * 16 + lrow;
                unsigned t4[4];
                ldmx4(t4, su32(&sm.b[r * KPAD + lcol]));
                b[0][0] = t4[0]; b[1][0] = t4[1]; b[0][1] = t4[2]; b[1][1] = t4[3];
            }
            #pragma unroll
            for (int mt = 0; mt < 2; mt++)
                #pragma unroll
                for (int nt = 0; nt < 2; nt++)
                    mma_f16(acc[mt][nt], ah[mt], b[nt]);
        }
        __syncthreads();
    }

    #pragma unroll
    for (int mt = 0; mt < 2; mt++)
        #pragma unroll
        for (int nt = 0; nt < 2; nt++)
            #pragma unroll
            for (int pp = 0; pp < 2; pp++){
                int row = m0 + warp_m * 32 + mt * 16 + (lane >> 2) + 8 * pp;
                int col = n0 + warp_n * 16 + nt * 8 + 2 * (lane & 3);
                float* dst = &g_xp[(size_t)row * GDIM + col];
                dst[0] = acc[mt][nt][2 * pp]     + g_bias[col];
                dst[1] = acc[mt][nt][2 * pp + 1] + g_bias[col + 1];
            }
}

// ---------------- persistent recurrence (fp16 single-pass, XOR swizzle) ----------------
__device__ __forceinline__ void load_chunk(unsigned abase_st, const __half* hsrc,
                                           int kt, int tid){
    #pragma unroll
    for (int i = 0; i < 4; i++){
        int u = tid + i * PTH;          // 0..2047
        int r = u >> 4;                 // 0..127 batch row
        int c16 = u & 15;               // 16B chunk in row
        const __half* src = hsrc + (size_t)r * HID + kt * 128 + c16 * 8;
        unsigned dst = abase_st + r * 256 + ((((c16 ^ r) & 7) | (c16 & 8)) << 4);
        cpasync16(dst, src);
    }
}

__global__ __launch_bounds__(PTH, 1)
void lstm_rec(const float* __restrict__ W_hh, const float* __restrict__ c0)
{
    extern __shared__ __align__(1024) char dyn[];
    const int tid  = threadIdx.x;
    const int lane = tid & 31;
    const int wid  = tid >> 5;
    const int warp_m = wid >> 2;    // 0..3 : 32 rows
    const int warp_n = wid & 3;     // 0..3 : 16 cols
    const int n0 = blockIdx.x * PBN;
    const unsigned wbase = su32(dyn + OFF_W);
    const unsigned abase = su32(dyn + OFF_A);

    // one-time: gather + convert W_hh slice -> fp16, XOR-swizzled 2048B rows
    for (int idx = tid; idx < PBN * (HID / 8); idx += PTH){
        int j  = idx >> 7;             // 0..63 (slice row)
        int c8 = idx & 127;            // 16B chunk in row
        int c  = c8 * 8;
        int g  = n0 + j;
        const float* src = W_hh + (size_t)((g & 3) * HID + (g >> 2)) * HID + c;
        float4 v0 = *reinterpret_cast<const float4*>(src);
        float4 v1 = *reinterpret_cast<const float4*>(src + 4);
        int sc = (c8 & ~7) | ((c8 ^ j) & 7);
        __half2* d = reinterpret_cast<__half2*>(dyn + OFF_W + j * 2048 + (sc << 4));
        d[0] = __floats2half2_rn(v0.x, v0.y);
        d[1] = __floats2half2_rn(v0.z, v0.w);
        d[2] = __floats2half2_rn(v1.x, v1.y);
        d[3] = __floats2half2_rn(v1.z, v1.w);
    }

    // register-resident cell state: 4 units per thread
    const int erow = tid >> 2;               // batch row
    const int q    = tid & 3;
    const int ub   = (n0 >> 2) + q * 4;      // first unit
    float creg[4];
    #pragma unroll
    for (int u = 0; u < 4; u++) creg[u] = c0[erow * HID + ub + u];
    __syncthreads();

    int sense = 0;
    for (int s = 0; s < S_LEN; s++){
        const __half* hsrc = g_hh[s & 1];

        // prefetch this thread's x_proj row segment (used in epilogue)
        const float* xpr = g_xp + ((size_t)s * NBATCH + erow) * GDIM + n0 + q * 16;
        float4 xv0 = *reinterpret_cast<const float4*>(xpr);
        float4 xv1 = *reinterpret_cast<const float4*>(xpr + 4);
        float4 xv2 = *reinterpret_cast<const float4*>(xpr + 8);
        float4 xv3 = *reinterpret_cast<const float4*>(xpr + 12);

        float acc[2][2][4];
        #pragma unroll
        for (int i = 0; i < 2; i++)
            #pragma unroll
            for (int j = 0; j < 2; j++)
                #pragma unroll
                for (int k = 0; k < 4; k++) acc[i][j][k] = 0.0f;

        load_chunk(abase + 0 * CHB, hsrc, 0, tid); CP_COMMIT();
        load_chunk(abase + 1 * CHB, hsrc, 1, tid); CP_COMMIT();

        for (int kt = 0; kt < NCH; kt++){
            if (kt + 2 < NCH){
                load_chunk(abase + ((kt + 2) % 3) * CHB, hsrc, kt + 2, tid);
                CP_COMMIT();
                CP_WAIT(2);
            } else if (kt == NCH - 2){
                CP_WAIT(1);
            } else {
                CP_WAIT(0);
            }
            __syncthreads();

            const unsigned ab = abase + (kt % 3) * CHB;
            #pragma unroll
            for (int kkl = 0; kkl < 8; kkl++){
                const int lrow = lane & 15;
                const int koff = kkl * 16 + ((lane >> 4) << 3);   // 0..127
                const int c16  = koff >> 3;                       // 0..15
                unsigned ah[2][4];
                #pragma unroll
                for (int mt = 0; mt < 2; mt++){
                    int r = warp_m * 32 + mt * 16 + lrow;
                    ldmx4(ah[mt], ab + r * 256 + ((((c16 ^ r) & 7) | (c16 & 8)) << 4));
                }
                unsigned b[2][2];
                {
                    int r = warp_n * 16 + lrow;
                    int c8 = (kt * 128 + koff) >> 3;              // 0..127
                    unsigned t4[4];
                    ldmx4(t4, wbase + r * 2048 + (((c8 & ~7) | ((c8 ^ r) & 7)) << 4));
                    b[0][0] = t4[0]; b[1][0] = t4[1]; b[0][1] = t4[2]; b[1][1] = t4[3];
                }
                #pragma unroll
                for (int mt = 0; mt < 2; mt++)
                    #pragma unroll
                    for (int nt = 0; nt < 2; nt++)
                        mma_f16(acc[mt][nt], ah[mt], b[nt]);
            }
            __syncthreads();
        }

        // stage gates (reuse stage-0 buffer: exactly 32KB)
        float* gates = (float*)(dyn + OFF_A);
        #pragma unroll
        for (int mt = 0; mt < 2; mt++)
            #pragma unroll
            for (int nt = 0; nt < 2; nt++)
                #pragma unroll
                for (int pp = 0; pp < 2; pp++){
                    int row = warp_m * 32 + mt * 16 + (lane >> 2) + 8 * pp;
                    int col = warp_n * 16 + nt * 8 + 2 * (lane & 3);
                    gates[row * PBN + col]     = acc[mt][nt][2 * pp];
                    gates[row * PBN + col + 1] = acc[mt][nt][2 * pp + 1];
                }
        __syncthreads();

        // fused LSTM elementwise: 4 units/thread, c in registers
        {
            const float* gr = &gates[erow * PBN + q * 16];
            float4 gv[4];
            gv[0] = *reinterpret_cast<const float4*>(gr);
            gv[1] = *reinterpret_cast<const float4*>(gr + 4);
            gv[2] = *reinterpret_cast<const float4*>(gr + 8);
            gv[3] = *reinterpret_cast<const float4*>(gr + 12);
            float4 xv[4] = {xv0, xv1, xv2, xv3};
            __half hbuf[4];
            #pragma unroll
            for (int u = 0; u < 4; u++){
                float ig = sigmoidf_(gv[u].x + xv[u].x);
                float fg = sigmoidf_(gv[u].y + xv[u].y);
                float gg = tanhf    (gv[u].z + xv[u].z);
                float og = sigmoidf_(gv[u].w + xv[u].w);
                creg[u] = fg * creg[u] + ig * gg;
                hbuf[u] = __float2half_rn(og * tanhf(creg[u]));
            }
            *reinterpret_cast<uint2*>(&g_hh[(s + 1) & 1][erow * HID + ub]) =
                *reinterpret_cast<uint2*>(hbuf);
        }

        grid_barrier(&sense);
    }
}

// ---------------- decode ----------------
__global__ void lstm_decode(const float* __restrict__ W_dec, const float* __restrict__ b_dec,
                            float* __restrict__ out){
    __shared__ float wsh[NOUT * HID];
    __shared__ float lsh[NOUT * NBATCH];
    __shared__ float red[2 * NOUT];
    int tid = threadIdx.x;
    for (int i = tid; i < NOUT * HID; i += 512) wsh[i] = W_dec[i];
    __syncthreads();
    int b = tid >> 2, q = tid & 3;
    const uint4* hp = reinterpret_cast<const uint4*>(&g_hh[0][b * HID + q * 256]);
    float a[4] = {0.f, 0.f, 0.f, 0.f};
    #pragma unroll 4
    for (int v = 0; v < 32; v++){
        uint4 pk = hp[v];
        const __half* h8 = reinterpret_cast<const __half*>(&pk);
        #pragma unroll
        for (int e = 0; e < 8; e++){
            float hv = __half2float(h8[e]);
            int kk = q * 256 + v * 8 + e;
            a[0] += hv * wsh[kk];
            a[1] += hv * wsh[HID + kk];
            a[2] += hv * wsh[2 * HID + kk];
            a[3] += hv * wsh[3 * HID + kk];
        }
    }
    #pragma unroll
    for (int o = 0; o < 4; o++){
        a[o] += __shfl_xor_sync(0xFFFFFFFFu, a[o], 1);
        a[o] += __shfl_xor_sync(0xFFFFFFFFu, a[o], 2);
    }
    if (q == 0){
        #pragma unroll
        for (int o = 0; o < 4; o++) lsh[o * NBATCH + b] = a[o] + b_dec[o];
    }
    __syncthreads();
    if (tid < NOUT){
        int o = tid;
        float m = -1e30f;
        for (int j = 0; j < NBATCH; j++) m = fmaxf(m, lsh[o * NBATCH + j]);
        float sum = 0.0f;
        for (int j = 0; j < NBATCH; j++) sum += expf(lsh[o * NBATCH + j] - m);
        red[o] = m; red[NOUT + o] = sum;
    }
    __syncthreads();
    if (tid < NBATCH){
        #pragma unroll
        for (int o = 0; o < NOUT; o++)
            out[tid * NOUT + o] = expf(lsh[o * NBATCH + tid] - red[o]) / red[NOUT + o];
    }
}

// ---------------- launch ----------------
extern "C" void kernel_launch(void* const* d_in, const int* in_sizes, int n_in,
                              void* d_out, int out_size)
{
    const float* inputs = (const float*)d_in[0];
    const float* h0     = (const float*)d_in[1];
    const float* c0     = (const float*)d_in[2];
    const float* W_ih   = (const float*)d_in[3];
    const float* W_hh   = (const float*)d_in[4];
    const float* b_ih   = (const float*)d_in[5];
    const float* b_hh   = (const float*)d_in[6];
    const float* W_dec  = (const float*)d_in[7];
    const float* b_dec  = (const float*)d_in[8];
    float* out = (float*)d_out;

    cudaFuncSetAttribute(lstm_rec, cudaFuncAttributeMaxDynamicSharedMemorySize, DYN_B);

    {
        int n8 = (S_LEN * NBATCH * IN_DIM) / 8;
        cvt_inputs<<<(n8 + 255) / 256, 256>>>(inputs);
        int nw = GDIM * (IN_DIM / 4);
        cvt_wih<<<(nw + 255) / 256, 256>>>(W_ih, b_ih, b_hh, h0);
    }

    dim3 g1(GDIM / BN, (S_LEN * NBATCH) / BM);
    xproj_gemm<<<g1, NTHREADS>>>();

    lstm_rec<<<PGRID, PTH, DYN_B>>>(W_hh, c0);

    lstm_decode<<<1, 512>>>(W_dec, b_dec, out);
}

// round 7
// speedup vs baseline: 2.3215x; 1.3709x over previous
#include <cuda_runtime.h>
#include <cuda_bf16.h>
#include <cuda_fp16.h>
#include <math.h>
#include <stdint.h>

#define S_LEN   512
#define NBATCH  128
#define IN_DIM  512
#define HID     1024
#define GDIM    4096   // interleaved: col g -> gate g&3, unit g>>2
#define NOUT    4

// phase-1 tiling
#define BM 64
#define BN 64
#define BKK 32
#define KPAD 40
#define NTHREADS 256

// recurrence: 128 CTAs = 2 row-halves x 64 col-tiles, each 64x64xK
#define PGRID 128
#define PTH 512                  // 16 warps
#define NCH 4                    // K chunks of 256
#define CHB 32768                // chunk: 64 rows x 512B
#define WB  131072               // W: 64 gate-cols x 2048B
#define OFF_W 0
#define OFF_A WB
#define DYN_B (WB + 3 * CHB)     // 229376

__device__ float  g_xp[(size_t)S_LEN * NBATCH * GDIM];   // x_proj (+bias), fp32
__device__ __half g_xh[(size_t)S_LEN * NBATCH * IN_DIM]; // inputs fp16
__device__ __half g_wih[(size_t)GDIM * IN_DIM];          // gathered W_ih fp16
__device__ float  g_bias[GDIM];                          // gathered b_ih+b_hh
__device__ __half g_hh[2][NBATCH * HID];                 // hidden fp16, dbl-buffered
__device__ int g_bar_count;
__device__ volatile int g_bar_phase;

__device__ __forceinline__ unsigned su32(const void* p){
    return (unsigned)__cvta_generic_to_shared(p);
}
__device__ __forceinline__ float sigmoidf_(float x){ return 1.0f / (1.0f + expf(-x)); }
__device__ __forceinline__ void cpasync16(unsigned saddr, const void* g){
    asm volatile("cp.async.cg.shared.global [%0], [%1], 16;" :: "r"(saddr), "l"(g));
}
#define CP_COMMIT() asm volatile("cp.async.commit_group;")
#define CP_WAIT(n)  asm volatile("cp.async.wait_group %0;" :: "n"(n))

__device__ __forceinline__ void ldmx4(unsigned* r, unsigned addr){
    asm volatile("ldmatrix.sync.aligned.m8n8.x4.shared.b16 {%0,%1,%2,%3}, [%4];"
        : "=r"(r[0]), "=r"(r[1]), "=r"(r[2]), "=r"(r[3]) : "r"(addr));
}
__device__ __forceinline__ void mma_f16(float* d, const unsigned* a, const unsigned* b){
    asm volatile("mma.sync.aligned.m16n8k16.row.col.f32.f16.f16.f32 "
        "{%0,%1,%2,%3},{%4,%5,%6,%7},{%8,%9},{%0,%1,%2,%3};"
        : "+f"(d[0]), "+f"(d[1]), "+f"(d[2]), "+f"(d[3])
        : "r"(a[0]), "r"(a[1]), "r"(a[2]), "r"(a[3]), "r"(b[0]), "r"(b[1]));
}

__device__ __forceinline__ void grid_barrier(int* sense){
    __threadfence();
    __syncthreads();
    if (threadIdx.x == 0){
        int target = *sense ^ 1;
        if (atomicAdd(&g_bar_count, 1) == PGRID - 1){
            atomicExch(&g_bar_count, 0);
            __threadfence();
            g_bar_phase = target;
        } else {
            while (g_bar_phase != target) __nanosleep(40);
        }
        *sense = target;
    }
    __syncthreads();
    __threadfence();
}

// ---------------- conversion pre-kernels ----------------
__global__ void cvt_inputs(const float* __restrict__ in){
    size_t i = (size_t)(blockIdx.x * blockDim.x + threadIdx.x) * 8;
    if (i < (size_t)S_LEN * NBATCH * IN_DIM){
        float4 v0 = *reinterpret_cast<const float4*>(in + i);
        float4 v1 = *reinterpret_cast<const float4*>(in + i + 4);
        __half2* d = reinterpret_cast<__half2*>(&g_xh[i]);
        d[0] = __floats2half2_rn(v0.x, v0.y);
        d[1] = __floats2half2_rn(v0.z, v0.w);
        d[2] = __floats2half2_rn(v1.x, v1.y);
        d[3] = __floats2half2_rn(v1.z, v1.w);
    }
}
__global__ void cvt_wih(const float* __restrict__ W_ih,
                        const float* __restrict__ b_ih, const float* __restrict__ b_hh,
                        const float* __restrict__ h0){
    int idx = blockIdx.x * blockDim.x + threadIdx.x;
    if (idx < GDIM * (IN_DIM / 4)){
        int g = idx >> 7;
        int c = (idx & 127) * 4;
        int r = (g & 3) * HID + (g >> 2);
        float4 v = *reinterpret_cast<const float4*>(W_ih + (size_t)r * IN_DIM + c);
        __half2* d = reinterpret_cast<__half2*>(&g_wih[(size_t)g * IN_DIM + c]);
        d[0] = __floats2half2_rn(v.x, v.y);
        d[1] = __floats2half2_rn(v.z, v.w);
        if (c == 0) g_bias[g] = b_ih[r] + b_hh[r];
    }
    if (idx < NBATCH * HID) g_hh[0][idx] = __float2half_rn(h0[idx]);
    if (idx == 0){ g_bar_count = 0; g_bar_phase = 0; }
}

// ---------------- phase 1: x_proj (single-pass fp16) ----------------
struct P1Smem {
    __half a[BM * KPAD];
    __half b[BN * KPAD];
};

__global__ __launch_bounds__(NTHREADS)
void xproj_gemm()
{
    __shared__ P1Smem sm;
    const int tid = threadIdx.x, lane = tid & 31, wid = tid >> 5;
    const int warp_m = wid >> 2, warp_n = wid & 3;
    const int m0 = blockIdx.y * BM, n0 = blockIdx.x * BN;

    float acc[2][2][4];
    #pragma unroll
    for (int i = 0; i < 2; i++)
        #pragma unroll
        for (int j = 0; j < 2; j++)
            #pragma unroll
            for (int k = 0; k < 4; k++) acc[i][j][k] = 0.0f;

    const int lrw = tid >> 2;
    const int lcc = (tid & 3) * 8;
    const __half* asrc = g_xh  + (size_t)(m0 + lrw) * IN_DIM + lcc;
    const __half* bsrc = g_wih + (size_t)(n0 + lrw) * IN_DIM + lcc;

    uint4 pa = *reinterpret_cast<const uint4*>(asrc);
    uint4 pb = *reinterpret_cast<const uint4*>(bsrc);

    const int KITERS = IN_DIM / BKK;
    for (int kt = 0; kt < KITERS; kt++){
        *reinterpret_cast<uint4*>(&sm.a[lrw * KPAD + lcc]) = pa;
        *reinterpret_cast<uint4*>(&sm.b[lrw * KPAD + lcc]) = pb;
        __syncthreads();
        if (kt + 1 < KITERS){
            pa = *reinterpret_cast<const uint4*>(asrc + (kt + 1) * BKK);
            pb = *reinterpret_cast<const uint4*>(bsrc + (kt + 1) * BKK);
        }
        #pragma unroll
        for (int kk = 0; kk < 2; kk++){
            const int lrow = lane & 15;
            const int lcol = kk * 16 + ((lane >> 4) << 3);
            unsigned ah[2][4];
            #pragma unroll
            for (int mt = 0; mt < 2; mt++){
                int r = warp_m * 32 + mt * 16 + lrow;
                ldmx4(ah[mt], su32(&sm.a[r * KPAD + lcol]));
            }
            unsigned b[2][2];
            {
                int r = warp_n * 16 + lrow;
                unsigned t4[4];
                ldmx4(t4, su32(&sm.b[r * KPAD + lcol]));
                b[0][0] = t4[0]; b[1][0] = t4[1]; b[0][1] = t4[2]; b[1][1] = t4[3];
            }
            #pragma unroll
            for (int mt = 0; mt < 2; mt++)
                #pragma unroll
                for (int nt = 0; nt < 2; nt++)
                    mma_f16(acc[mt][nt], ah[mt], b[nt]);
        }
        __syncthreads();
    }

    #pragma unroll
    for (int mt = 0; mt < 2; mt++)
        #pragma unroll
        for (int nt = 0; nt < 2; nt++)
            #pragma unroll
            for (int pp = 0; pp < 2; pp++){
                int row = m0 + warp_m * 32 + mt * 16 + (lane >> 2) + 8 * pp;
                int col = n0 + warp_n * 16 + nt * 8 + 2 * (lane & 3);
                float* dst = &g_xp[(size_t)row * GDIM + col];
                dst[0] = acc[mt][nt][2 * pp]     + g_bias[col];
                dst[1] = acc[mt][nt][2 * pp + 1] + g_bias[col + 1];
            }
}

// ---------------- persistent recurrence (M-split, fp16, 128 CTAs) ----------------
__device__ __forceinline__ void load_chunk(unsigned abase_st, const __half* hsrc,
                                           int m0, int kt, int tid){
    #pragma unroll
    for (int i = 0; i < 4; i++){
        int u = tid + i * PTH;          // 0..2047
        int r = u >> 5;                 // 0..63 local batch row
        int c16 = u & 31;               // 16B chunk in 512B row
        const __half* src = hsrc + (size_t)(m0 + r) * HID + kt * 256 + c16 * 8;
        unsigned dst = abase_st + r * 512 + ((((c16 ^ r) & 7) | (c16 & 24)) << 4);
        cpasync16(dst, src);
    }
}

__global__ __launch_bounds__(PTH, 1)
void lstm_rec(const float* __restrict__ W_hh, const float* __restrict__ c0)
{
    extern __shared__ __align__(1024) char dyn[];
    const int tid  = threadIdx.x;
    const int lane = tid & 31;
    const int wid  = tid >> 5;
    const int warp_m = wid >> 2;    // 0..3 : 16 rows each
    const int warp_n = wid & 3;     // 0..3 : 16 cols each
    const int m0 = (blockIdx.x & 1) * 64;     // row half
    const int n0 = (blockIdx.x >> 1) * 64;    // col tile
    const unsigned wbase = su32(dyn + OFF_W);
    const unsigned abase = su32(dyn + OFF_A);

    // one-time: gather + convert W_hh slice -> fp16, XOR-swizzled 2048B rows
    for (int idx = tid; idx < 64 * (HID / 8); idx += PTH){
        int j  = idx >> 7;             // 0..63 gate col
        int c8 = idx & 127;
        int c  = c8 * 8;
        int g  = n0 + j;
        const float* src = W_hh + (size_t)((g & 3) * HID + (g >> 2)) * HID + c;
        float4 v0 = *reinterpret_cast<const float4*>(src);
        float4 v1 = *reinterpret_cast<const float4*>(src + 4);
        int sc = (c8 & ~7) | ((c8 ^ j) & 7);
        __half2* d = reinterpret_cast<__half2*>(dyn + OFF_W + j * 2048 + (sc << 4));
        d[0] = __floats2half2_rn(v0.x, v0.y);
        d[1] = __floats2half2_rn(v0.z, v0.w);
        d[2] = __floats2half2_rn(v1.x, v1.y);
        d[3] = __floats2half2_rn(v1.z, v1.w);
    }

    // register-resident cell state: 2 units per thread
    const int erow = tid >> 3;               // 0..63 local batch row
    const int q    = tid & 7;                // 8 unit-pairs per row
    const int grow = m0 + erow;              // global batch row
    const int ub   = (n0 >> 2) + q * 2;      // first unit
    float creg0 = c0[grow * HID + ub];
    float creg1 = c0[grow * HID + ub + 1];
    __syncthreads();

    int sense = 0;
    for (int s = 0; s < S_LEN; s++){
        const __half* hsrc = g_hh[s & 1];

        // prefetch x_proj segment for epilogue (2 units = 8 floats)
        const float* xpr = g_xp + ((size_t)s * NBATCH + grow) * GDIM + n0 + q * 8;
        float4 xv0 = *reinterpret_cast<const float4*>(xpr);
        float4 xv1 = *reinterpret_cast<const float4*>(xpr + 4);

        float acc[2][4];
        #pragma unroll
        for (int j = 0; j < 2; j++)
            #pragma unroll
            for (int k = 0; k < 4; k++) acc[j][k] = 0.0f;

        load_chunk(abase + 0 * CHB, hsrc, m0, 0, tid); CP_COMMIT();
        load_chunk(abase + 1 * CHB, hsrc, m0, 1, tid); CP_COMMIT();

        for (int kt = 0; kt < NCH; kt++){
            if (kt + 2 < NCH){
                load_chunk(abase + ((kt + 2) % 3) * CHB, hsrc, m0, kt + 2, tid);
                CP_COMMIT();
                CP_WAIT(2);
            } else if (kt == NCH - 2){
                CP_WAIT(1);
            } else {
                CP_WAIT(0);
            }
            __syncthreads();

            const unsigned ab = abase + (kt % 3) * CHB;
            #pragma unroll
            for (int kkl = 0; kkl < 16; kkl++){
                const int lrow = lane & 15;
                const int koff = kkl * 16 + ((lane >> 4) << 3);   // 0..255
                const int c16  = koff >> 3;                       // 0..31
                unsigned ah[4];
                {
                    int r = warp_m * 16 + lrow;
                    ldmx4(ah, ab + r * 512 + ((((c16 ^ r) & 7) | (c16 & 24)) << 4));
                }
                unsigned b[2][2];
                {
                    int r = warp_n * 16 + lrow;
                    int c8 = (kt * 256 + koff) >> 3;              // 0..127
                    unsigned t4[4];
                    ldmx4(t4, wbase + r * 2048 + (((c8 & ~7) | ((c8 ^ r) & 7)) << 4));
                    b[0][0] = t4[0]; b[1][0] = t4[1]; b[0][1] = t4[2]; b[1][1] = t4[3];
                }
                #pragma unroll
                for (int nt = 0; nt < 2; nt++)
                    mma_f16(acc[nt], ah, b[nt]);
            }
            __syncthreads();
        }

        // stage gates (64x64 fp32 = 16KB, reuse stage-0 buffer)
        float* gates = (float*)(dyn + OFF_A);
        #pragma unroll
        for (int nt = 0; nt < 2; nt++)
            #pragma unroll
            for (int pp = 0; pp < 2; pp++){
                int row = warp_m * 16 + (lane >> 2) + 8 * pp;
                int col = warp_n * 16 + nt * 8 + 2 * (lane & 3);
                gates[row * 64 + col]     = acc[nt][2 * pp];
                gates[row * 64 + col + 1] = acc[nt][2 * pp + 1];
            }
        __syncthreads();

        // fused LSTM elementwise: 2 units/thread, c in registers
        {
            const float* gr = &gates[erow * 64 + q * 8];
            float4 g0 = *reinterpret_cast<const float4*>(gr);
            float4 g1 = *reinterpret_cast<const float4*>(gr + 4);

            float ig = sigmoidf_(g0.x + xv0.x);
            float fg = sigmoidf_(g0.y + xv0.y);
            float gg = tanhf    (g0.z + xv0.z);
            float og = sigmoidf_(g0.w + xv0.w);
            creg0 = fg * creg0 + ig * gg;
            float hv0 = og * tanhf(creg0);

            ig = sigmoidf_(g1.x + xv1.x);
            fg = sigmoidf_(g1.y + xv1.y);
            gg = tanhf    (g1.z + xv1.z);
            og = sigmoidf_(g1.w + xv1.w);
            creg1 = fg * creg1 + ig * gg;
            float hv1 = og * tanhf(creg1);

            *reinterpret_cast<__half2*>(&g_hh[(s + 1) & 1][grow * HID + ub]) =
                __halves2half2(__float2half_rn(hv0), __float2half_rn(hv1));
        }

        grid_barrier(&sense);
    }
}

// ---------------- decode ----------------
__global__ void lstm_decode(const float* __restrict__ W_dec, const float* __restrict__ b_dec,
                            float* __restrict__ out){
    __shared__ float wsh[NOUT * HID];
    __shared__ float lsh[NOUT * NBATCH];
    __shared__ float red[2 * NOUT];
    int tid = threadIdx.x;
    for (int i = tid; i < NOUT * HID; i += 512) wsh[i] = W_dec[i];
    __syncthreads();
    int b = tid >> 2, q = tid & 3;
    const uint4* hp = reinterpret_cast<const uint4*>(&g_hh[0][b * HID + q * 256]);
    float a[4] = {0.f, 0.f, 0.f, 0.f};
    #pragma unroll 4
    for (int v = 0; v < 32; v++){
        uint4 pk = hp[v];
        const __half* h8 = reinterpret_cast<const __half*>(&pk);
        #pragma unroll
        for (int e = 0; e < 8; e++){
            float hv = __half2float(h8[e]);
            int kk = q * 256 + v * 8 + e;
            a[0] += hv * wsh[kk];
            a[1] += hv * wsh[HID + kk];
            a[2] += hv * wsh[2 * HID + kk];
            a[3] += hv * wsh[3 * HID + kk];
        }
    }
    #pragma unroll
    for (int o = 0; o < 4; o++){
        a[o] += __shfl_xor_sync(0xFFFFFFFFu, a[o], 1);
        a[o] += __shfl_xor_sync(0xFFFFFFFFu, a[o], 2);
    }
    if (q == 0){
        #pragma unroll
        for (int o = 0; o < 4; o++) lsh[o * NBATCH + b] = a[o] + b_dec[o];
    }
    __syncthreads();
    if (tid < NOUT){
        int o = tid;
        float m = -1e30f;
        for (int j = 0; j < NBATCH; j++) m = fmaxf(m, lsh[o * NBATCH + j]);
        float sum = 0.0f;
        for (int j = 0; j < NBATCH; j++) sum += expf(lsh[o * NBATCH + j] - m);
        red[o] = m; red[NOUT + o] = sum;
    }
    __syncthreads();
    if (tid < NBATCH){
        #pragma unroll
        for (int o = 0; o < NOUT; o++)
            out[tid * NOUT + o] = expf(lsh[o * NBATCH + tid] - red[o]) / red[NOUT + o];
    }
}

// ---------------- launch ----------------
extern "C" void kernel_launch(void* const* d_in, const int* in_sizes, int n_in,
                              void* d_out, int out_size)
{
    const float* inputs = (const float*)d_in[0];
    const float* h0     = (const float*)d_in[1];
    const float* c0     = (const float*)d_in[2];
    const float* W_ih   = (const float*)d_in[3];
    const float* W_hh   = (const float*)d_in[4];
    const float* b_ih   = (const float*)d_in[5];
    const float* b_hh   = (const float*)d_in[6];
    const float* W_dec  = (const float*)d_in[7];
    const float* b_dec  = (const float*)d_in[8];
    float* out = (float*)d_out;

    cudaFuncSetAttribute(lstm_rec, cudaFuncAttributeMaxDynamicSharedMemorySize, DYN_B);

    {
        int n8 = (S_LEN * NBATCH * IN_DIM) / 8;
        cvt_inputs<<<(n8 + 255) / 256, 256>>>(inputs);
        int nw = GDIM * (IN_DIM / 4);
        cvt_wih<<<(nw + 255) / 256, 256>>>(W_ih, b_ih, b_hh, h0);
    }

    dim3 g1(GDIM / BN, (S_LEN * NBATCH) / BM);
    xproj_gemm<<<g1, NTHREADS>>>();

    lstm_rec<<<PGRID, PTH, DYN_B>>>(W_hh, c0);

    lstm_decode<<<1, 512>>>(W_dec, b_dec, out);
}